// round 13
// baseline (speedup 1.0000x reference)
#include <cuda_runtime.h>
#include <cuda_fp16.h>
#include <cstdint>

// Problem shape (fixed by dataset): B=16, S=1024, D=1024, A=256
#define B_    16
#define S_    1024
#define D_    1024
#define A_    256
#define NSEG  64
#define SEGL  16      // S_/NSEG

// ---------------- scratch (device globals; no allocation allowed) -------------
__device__ float g_s  [B_ * S_];             // final attention scores
__device__ float g_w  [B_ * S_];             // exp(s - max_b)
__device__ float g_zp [B_ * S_];             // inclusive prefix sum of w
__device__ float g_zs [B_ * S_];             // inclusive suffix sum of w
__device__ float g_ps [B_ * NSEG * D_];      // segment partial sums of w*h
__device__ float g_cp [B_ * NSEG * D_];      // exclusive prefix carries
__device__ float g_cs [B_ * NSEG * D_];      // exclusive suffix carries
__device__ float g_tot[B_ * D_];             // total sum of w*h
// fp16 W1, transposed (n-major), PRE-SWIZZLED: 16 K64-chunks x 32KB.
__device__ uint4 g_Bq[16 * 2048];

// ---------------- small float4 helpers ----------------------------------------
__device__ __forceinline__ float4 f4fma(float s, float4 h, float4 acc) {
    acc.x = fmaf(s, h.x, acc.x); acc.y = fmaf(s, h.y, acc.y);
    acc.z = fmaf(s, h.z, acc.z); acc.w = fmaf(s, h.w, acc.w);
    return acc;
}
__device__ __forceinline__ float4 f4scale(float4 a, float s) {
    return make_float4(a.x * s, a.y * s, a.z * s, a.w * s);
}

// ---------------- portable PTX helpers (sm_80-class; no 'a' features) ---------
__device__ __forceinline__ uint32_t smem_u32(const void* p) {
    uint32_t a;
    asm("{ .reg .u64 t; cvta.to.shared.u64 t, %1; cvt.u32.u64 %0, t; }" : "=r"(a) : "l"(p));
    return a;
}
__device__ __forceinline__ void ldsm_x4(uint32_t* r, uint32_t addr) {
    asm volatile("ldmatrix.sync.aligned.m8n8.x4.shared.b16 {%0,%1,%2,%3}, [%4];"
                 : "=r"(r[0]), "=r"(r[1]), "=r"(r[2]), "=r"(r[3]) : "r"(addr));
}
__device__ __forceinline__ void mma_f16(float* c, const uint32_t* a, const uint32_t* b) {
    asm volatile(
        "mma.sync.aligned.m16n8k16.row.col.f32.f16.f16.f32 "
        "{%0,%1,%2,%3}, {%4,%5,%6,%7}, {%8,%9}, {%0,%1,%2,%3};"
        : "+f"(c[0]), "+f"(c[1]), "+f"(c[2]), "+f"(c[3])
        : "r"(a[0]), "r"(a[1]), "r"(a[2]), "r"(a[3]), "r"(b[0]), "r"(b[1]));
}
#define CP_ASYNC16(dst, src) \
    asm volatile("cp.async.cg.shared.global [%0], [%1], 16;" :: "r"(dst), "l"(src))
#define CP_COMMIT() asm volatile("cp.async.commit_group;" ::: "memory")
#define CP_WAIT0()  asm volatile("cp.async.wait_group 0;" ::: "memory")

#define SWZ(x) ((x) ^ (((x) >> 3) & 0x70))

__device__ __forceinline__ float fast_tanh(float z) {
    const float ez = __expf(2.f * z);
    return 1.f - __fdividef(2.f, ez + 1.f);
}
__device__ __forceinline__ uint32_t h2pack(float a, float b) {
    const __half2 h = __floats2half2_rn(a, b);
    return *reinterpret_cast<const uint32_t*>(&h);
}

// ==============================================================================
// k_splitB: W1 [K=1024][N=256] fp32 -> fp16 n-major [n][k], 16 pre-swizzled
// 32KB K64-chunk images (row n = 64 fp16 = 128B).
// ==============================================================================
__global__ __launch_bounds__(256)
void k_splitB(const float* __restrict__ W1)
{
    const int p  = blockIdx.x * 256 + threadIdx.x;   // 0..131071
    const int n  = p & 255;
    const int kp = p >> 8;                           // 0..511
    const int k  = kp * 2;
    const int c  = k >> 6;                           // K64 chunk
    const int kk = k & 63;

    const float x0 = W1[(size_t)k * A_ + n];
    const float x1 = W1[(size_t)(k + 1) * A_ + n];
    char* img = reinterpret_cast<char*>(g_Bq) + (size_t)c * 32768;
    const uint32_t off = SWZ((uint32_t)n * 128 + (uint32_t)kk * 2);
    *reinterpret_cast<uint32_t*>(img + off) = h2pack(x0, x1);
}

// ==============================================================================
// k_scores_hmma: single-product fp16 GEMM via mma.sync.m16n8k16.f16.
// CTA tile 64(M) x 256(N, full), BK=64, 256 threads = 8 warps (2M x 4N),
// warp tile 32x64.  __launch_bounds__(256, 2): 2 CTAs/SM, one wave.
// (Frozen: best observed GEMM configuration, R10/R12.)
// ==============================================================================
#define OFF_V     0
#define OFF_B1    1024
#define OFF_DATA  4096
#define SB_OFF    8192       // B image within stage
#define STAGE_SZ  40960
#define SMEM_BYTES (OFF_DATA + 2 * STAGE_SZ)   // 86016

__global__ __launch_bounds__(256, 2)
void k_scores_hmma(const float* __restrict__ H, const float* __restrict__ b1,
                   const float* __restrict__ v)
{
    extern __shared__ char smem[];
    const uint32_t sb = smem_u32(smem);
    const int tid  = threadIdx.x;
    const int lane = tid & 31;
    const int wid  = tid >> 5;
    const int wm   = (wid & 1) * 32;       // warp M offset (0/32)
    const int wn   = (wid >> 1) * 64;      // warp N offset (0/64/128/192)
    const int m0   = blockIdx.x * 64;

    ((float*)(smem + OFF_V))[tid]  = v[tid];
    ((float*)(smem + OFF_B1))[tid] = b1[tid];

    // ---- A global load mapping: 64 rows x 64 floats, 16 floats per thread ----
    const int arow = tid >> 2;             // 0..63
    const int acol = (tid & 3) * 16;       // 0/16/32/48
    const float4* Ag = reinterpret_cast<const float4*>(H + (size_t)(m0 + arow) * D_ + acol);
    const uint32_t a_sts0 = SWZ((uint32_t)arow * 128 + (uint32_t)acol * 2);
    const uint32_t a_sts1 = SWZ((uint32_t)arow * 128 + (uint32_t)acol * 2 + 16);

    // ---- ldmatrix lane offsets (bytes within tile, pre-swizzle) ----
    uint32_t aoff[2];
#pragma unroll
    for (int mt = 0; mt < 2; mt++)
        aoff[mt] = (uint32_t)(wm + mt * 16 + (lane & 15)) * 128 + (uint32_t)(lane >> 4) * 16;
    const int bn = (lane & 7) + ((lane >> 4) << 3);
    const uint32_t b_kb = (uint32_t)((lane >> 3) & 1) * 16;
    uint32_t boff[4];
#pragma unroll
    for (int np = 0; np < 4; np++)
        boff[np] = (uint32_t)(wn + np * 16 + bn) * 128 + b_kb;

    float acc[2][8][4];
#pragma unroll
    for (int mt = 0; mt < 2; mt++)
#pragma unroll
        for (int nt = 0; nt < 8; nt++)
#pragma unroll
            for (int e = 0; e < 4; e++) acc[mt][nt][e] = 0.f;

    // load this thread's 16 A floats of chunk c and convert immediately
    auto loadA = [&](int c, uint4& q0, uint4& q1) {
        float4 x0 = __ldg(Ag + c * 16);
        float4 x1 = __ldg(Ag + c * 16 + 1);
        q0 = make_uint4(h2pack(x0.x, x0.y), h2pack(x0.z, x0.w),
                        h2pack(x1.x, x1.y), h2pack(x1.z, x1.w));
        x0 = __ldg(Ag + c * 16 + 2);
        x1 = __ldg(Ag + c * 16 + 3);
        q1 = make_uint4(h2pack(x0.x, x0.y), h2pack(x0.z, x0.w),
                        h2pack(x1.x, x1.y), h2pack(x1.z, x1.w));
    };

    // ---- prologue: fill stage 0 ----
    {
        const uint32_t st = sb + OFF_DATA;
#pragma unroll
        for (int u = 0; u < 8; u++)
            CP_ASYNC16(st + SB_OFF + (tid + u * 256) * 16, (const char*)(g_Bq + tid + u * 256));
        CP_COMMIT();
        uint4 q0, q1;
        loadA(0, q0, q1);
        *reinterpret_cast<uint4*>(smem + OFF_DATA + a_sts0) = q0;
        *reinterpret_cast<uint4*>(smem + OFF_DATA + a_sts1) = q1;
        CP_WAIT0();
        __syncthreads();
    }

#pragma unroll 1
    for (int c = 0; c < 16; c++) {
        const uint32_t cur = sb + OFF_DATA + (uint32_t)(c & 1) * STAGE_SZ;
        const uint32_t nxt = sb + OFF_DATA + (uint32_t)((c + 1) & 1) * STAGE_SZ;
        const bool more = (c + 1) < 16;

        uint4 q0, q1;
        if (more) {
#pragma unroll
            for (int u = 0; u < 8; u++)
                CP_ASYNC16(nxt + SB_OFF + (tid + u * 256) * 16,
                           (const char*)(g_Bq + (c + 1) * 2048 + tid + u * 256));
            CP_COMMIT();
            loadA(c + 1, q0, q1);
        }

        // ---- compute: 4 k16 steps per chunk (6 LDSM -> 16 HMMA each) ----
#pragma unroll
        for (int ks = 0; ks < 4; ks++) {
            uint32_t ah[2][4];
#pragma unroll
            for (int mt = 0; mt < 2; mt++)
                ldsm_x4(ah[mt], cur + SWZ(aoff[mt] + ks * 32));
            uint32_t bh[4][4];
#pragma unroll
            for (int np = 0; np < 4; np++)
                ldsm_x4(bh[np], cur + SB_OFF + SWZ(boff[np] + ks * 32));
#pragma unroll
            for (int mt = 0; mt < 2; mt++)
#pragma unroll
                for (int np = 0; np < 4; np++) {
                    mma_f16(acc[mt][np*2],   ah[mt], bh[np]);
                    mma_f16(acc[mt][np*2+1], ah[mt], bh[np] + 2);
                }
        }

        if (more) {
            const uint32_t nxt_off = OFF_DATA + (uint32_t)((c + 1) & 1) * STAGE_SZ;
            *reinterpret_cast<uint4*>(smem + nxt_off + a_sts0) = q0;
            *reinterpret_cast<uint4*>(smem + nxt_off + a_sts1) = q1;
            CP_WAIT0();
            __syncthreads();
        }
    }
    __syncthreads();   // stage area about to be reused as reduction buffer

    // ---- epilogue: s[m] = sum_n v[n] * tanh(acc + b1[n]) ----
    {
        const float* vs  = (const float*)(smem + OFF_V);
        const float* b1s = (const float*)(smem + OFF_B1);
        float* red = (float*)(smem + OFF_DATA);   // [64][4]
        const int nw = wid >> 1;

#pragma unroll
        for (int mt = 0; mt < 2; mt++) {
            float s0 = 0.f, s1 = 0.f;
#pragma unroll
            for (int nt = 0; nt < 8; nt++) {
#pragma unroll
                for (int e = 0; e < 2; e++) {
                    const int col = wn + nt * 8 + (lane & 3) * 2 + e;
                    s0 = fmaf(vs[col], fast_tanh(acc[mt][nt][e]     + b1s[col]), s0);
                    s1 = fmaf(vs[col], fast_tanh(acc[mt][nt][e + 2] + b1s[col]), s1);
                }
            }
            s0 += __shfl_xor_sync(0xffffffffu, s0, 1);
            s0 += __shfl_xor_sync(0xffffffffu, s0, 2);
            s1 += __shfl_xor_sync(0xffffffffu, s1, 1);
            s1 += __shfl_xor_sync(0xffffffffu, s1, 2);
            if ((lane & 3) == 0) {
                const int r0 = wm + mt * 16 + (lane >> 2);
                red[r0 * 4 + nw]       = s0;
                red[(r0 + 8) * 4 + nw] = s1;
            }
        }
        __syncthreads();
        if (tid < 64) {
            const float s = red[tid * 4] + red[tid * 4 + 1] + red[tid * 4 + 2] + red[tid * 4 + 3];
            g_s[m0 + tid] = s;
        }
    }
}

// ==============================================================================
// K2-prep: per batch b — max, w = exp(s - max), inclusive prefix (Zp) and
// inclusive suffix (Zs) scans of w. One block of 1024 threads per batch.
// ==============================================================================
__global__ __launch_bounds__(1024)
void k_prep()
{
    const int b = blockIdx.x;
    const int t = threadIdx.x;
    const int lane = t & 31;
    const int warp = t >> 5;

    __shared__ float sh[S_];
    __shared__ float red[32];
    __shared__ float bmax;

    const int base = b * S_;
    float s = g_s[base + t];

    float m = s;
#pragma unroll
    for (int off = 16; off > 0; off >>= 1)
        m = fmaxf(m, __shfl_xor_sync(0xffffffffu, m, off));
    if (lane == 0) red[warp] = m;
    __syncthreads();
    if (t == 0) {
        float mm = red[0];
        for (int i = 1; i < 32; i++) mm = fmaxf(mm, red[i]);
        bmax = mm;
    }
    __syncthreads();

    const float w = expf(s - bmax);
    g_w[base + t] = w;
    sh[t] = w;
    __syncthreads();

    float ps = w;
#pragma unroll
    for (int off = 1; off < 32; off <<= 1) {
        float n = __shfl_up_sync(0xffffffffu, ps, off);
        if (lane >= off) ps += n;
    }
    if (lane == 31) red[warp] = ps;
    __syncthreads();
    if (warp == 0) {
        float x = red[lane];
#pragma unroll
        for (int off = 1; off < 32; off <<= 1) {
            float n = __shfl_up_sync(0xffffffffu, x, off);
            if (lane >= off) x += n;
        }
        red[lane] = x;
    }
    __syncthreads();
    g_zp[base + t] = ps + (warp ? red[warp - 1] : 0.f);
    __syncthreads();

    float wr = sh[(S_ - 1) - t];
    float pr = wr;
#pragma unroll
    for (int off = 1; off < 32; off <<= 1) {
        float n = __shfl_up_sync(0xffffffffu, pr, off);
        if (lane >= off) pr += n;
    }
    if (lane == 31) red[warp] = pr;
    __syncthreads();
    if (warp == 0) {
        float x = red[lane];
#pragma unroll
        for (int off = 1; off < 32; off <<= 1) {
            float n = __shfl_up_sync(0xffffffffu, x, off);
            if (lane >= off) x += n;
        }
        red[lane] = x;
    }
    __syncthreads();
    g_zs[base + (S_ - 1) - t] = pr + (warp ? red[warp - 1] : 0.f);
}

// ==============================================================================
// K2-passA: segment partial sums  PS[b][seg][d] = sum_{l in seg} w[l]*h[b,l,d]
// 128 threads, TWO float4 columns per thread (d, d+512) -> two independent
// accumulator chains and double the loads in flight (MLP).
// ==============================================================================
__global__ __launch_bounds__(128)
void k_passA(const float* __restrict__ H)
{
    const int b   = blockIdx.x;
    const int seg = blockIdx.y;
    const int t   = threadIdx.x;
    const int d   = t * 4;

    __shared__ float ws[SEGL];
    if (t < SEGL) ws[t] = g_w[b * S_ + seg * SEGL + t];
    __syncthreads();

    const float* hp = H + ((size_t)b * S_ + seg * SEGL) * D_ + d;
    float4 acc0 = make_float4(0.f, 0.f, 0.f, 0.f);
    float4 acc1 = make_float4(0.f, 0.f, 0.f, 0.f);
#pragma unroll
    for (int l = 0; l < SEGL; l++) {
        const float wl = ws[l];
        float4 h0 = *reinterpret_cast<const float4*>(hp + (size_t)l * D_);
        float4 h1 = *reinterpret_cast<const float4*>(hp + (size_t)l * D_ + 512);
        acc0 = f4fma(wl, h0, acc0);
        acc1 = f4fma(wl, h1, acc1);
    }
    float* pso = g_ps + ((size_t)b * NSEG + seg) * D_ + d;
    *reinterpret_cast<float4*>(pso)       = acc0;
    *reinterpret_cast<float4*>(pso + 512) = acc1;
}

// ==============================================================================
// k_segscan: per (b,d) exclusive scans over segment partials + totals.
// grid (B, 4, 2): z=0 prefix (+total), z=1 suffix.  No register caching of
// partials: suffix pass re-reads g_ps from L2 (4MB, resident).
// ==============================================================================
__global__ __launch_bounds__(256)
void k_segscan()
{
    const int b = blockIdx.x;
    const int d = blockIdx.y * 256 + threadIdx.x;
    const size_t base = (size_t)b * NSEG * D_ + d;

    if (blockIdx.z == 0) {
        float run = 0.f;
#pragma unroll
        for (int s = 0; s < NSEG; s++) {
            g_cp[base + (size_t)s * D_] = run;
            run += g_ps[base + (size_t)s * D_];
        }
        g_tot[b * D_ + d] = run;
    } else {
        float run = 0.f;
#pragma unroll
        for (int s = NSEG - 1; s >= 0; s--) {
            g_cs[base + (size_t)s * D_] = run;
            run += g_ps[base + (size_t)s * D_];
        }
    }
}

// ==============================================================================
// K2-passB: final pooled output (carries precomputed by k_segscan).
//  pt==0 (prefix):  out[j,d] = P_j[d]            / (Zp_j       * (j+1))
//  pt==1 (postfix): out[j,d] = Sfx_j[d]          / (Zs_j       * (S-j))
//  pt==2 (cloze):   out[j,d] = (T[d]-w_j h[j,d]) / ((Zt - w_j) * (S-1))
// ==============================================================================
__global__ __launch_bounds__(256)
void k_passB(const float* __restrict__ H, const int* __restrict__ pt_ids,
             float* __restrict__ out)
{
    const int b   = blockIdx.x;
    const int seg = blockIdx.y;
    const int t   = threadIdx.x;
    const int d   = t * 4;
    const int pt  = pt_ids[b];

    __shared__ float ws[SEGL], zps[SEGL], zss[SEGL];
    if (t < SEGL) {
        const int l = seg * SEGL + t;
        ws[t]  = g_w [b * S_ + l];
        zps[t] = g_zp[b * S_ + l];
        zss[t] = g_zs[b * S_ + l];
    }
    __syncthreads();

    const size_t cbase = ((size_t)b * NSEG + seg) * D_ + d;
    float4 carry;
    if (pt == 0)      carry = *reinterpret_cast<const float4*>(&g_cp[cbase]);
    else if (pt == 1) carry = *reinterpret_cast<const float4*>(&g_cs[cbase]);
    else              carry = *reinterpret_cast<const float4*>(&g_tot[b * D_ + d]);

    const float* hp = H   + ((size_t)b * S_ + seg * SEGL) * D_ + d;
    float*       op = out + ((size_t)b * S_ + seg * SEGL) * D_ + d;

    if (pt == 0) {
        float4 acc = carry;
#pragma unroll
        for (int i = 0; i < SEGL; i++) {
            const int j = seg * SEGL + i;
            float4 h4 = *reinterpret_cast<const float4*>(hp + (size_t)i * D_);
            acc = f4fma(ws[i], h4, acc);
            const float inv = 1.f / (zps[i] * (float)(j + 1));
            *reinterpret_cast<float4*>(op + (size_t)i * D_) = f4scale(acc, inv);
        }
    } else if (pt == 1) {
        float4 acc = carry;
#pragma unroll
        for (int i = SEGL - 1; i >= 0; i--) {
            const int j = seg * SEGL + i;
            float4 h4 = *reinterpret_cast<const float4*>(hp + (size_t)i * D_);
            acc = f4fma(ws[i], h4, acc);
            const float inv = 1.f / (zss[i] * (float)(S_ - j));
            *reinterpret_cast<float4*>(op + (size_t)i * D_) = f4scale(acc, inv);
        }
    } else {
        const float ztot = g_zp[b * S_ + (S_ - 1)];
        const float invcnt = 1.f / (float)(S_ - 1);
#pragma unroll
        for (int i = 0; i < SEGL; i++) {
            float4 h4 = *reinterpret_cast<const float4*>(hp + (size_t)i * D_);
            const float wl = ws[i];
            const float inv = invcnt / (ztot - wl);
            float4 num = f4fma(-wl, h4, carry);
            *reinterpret_cast<float4*>(op + (size_t)i * D_) = f4scale(num, inv);
        }
    }
}

// ==============================================================================
extern "C" void kernel_launch(void* const* d_in, const int* in_sizes, int n_in,
                              void* d_out, int out_size)
{
    const float* H   = (const float*)d_in[0];
    const float* W1  = (const float*)d_in[1];
    const float* b1  = (const float*)d_in[2];
    const float* v   = (const float*)d_in[3];
    const int*   pt  = (const int*)  d_in[4];
    float*       out = (float*)d_out;

    cudaFuncSetAttribute(k_scores_hmma, cudaFuncAttributeMaxDynamicSharedMemorySize, SMEM_BYTES);

    k_splitB     <<<512, 256>>>(W1);
    k_scores_hmma<<<(B_ * S_) / 64, 256, SMEM_BYTES>>>(H, b1, v);
    k_prep       <<<B_, S_>>>();
    k_passA      <<<dim3(B_, NSEG), 128>>>(H);      // launch #4 -> profiled
    k_segscan    <<<dim3(B_, 4, 2), 256>>>();
    k_passB      <<<dim3(B_, NSEG), 256>>>(H, pt, out);
}

// round 14
// speedup vs baseline: 1.1275x; 1.1275x over previous
#include <cuda_runtime.h>
#include <cuda_fp16.h>
#include <cstdint>

// Problem shape (fixed by dataset): B=16, S=1024, D=1024, A=256
#define B_    16
#define S_    1024
#define D_    1024
#define A_    256
#define NSEG  64
#define SEGL  16      // S_/NSEG

// ---------------- scratch (device globals; no allocation allowed) -------------
__device__ float g_s  [B_ * S_];             // final attention scores
__device__ float g_w  [B_ * S_];             // exp(s - max_b)
__device__ float g_zp [B_ * S_];             // inclusive prefix sum of w
__device__ float g_zs [B_ * S_];             // inclusive suffix sum of w
__device__ float g_ps [B_ * NSEG * D_];      // segment partial sums of w*h
__device__ float g_cp [B_ * NSEG * D_];      // exclusive prefix carries
__device__ float g_cs [B_ * NSEG * D_];      // exclusive suffix carries
__device__ float g_tot[B_ * D_];             // total sum of w*h
// fp16 W1, transposed (n-major), PRE-SWIZZLED: 16 K64-chunks x 32KB.
__device__ uint4 g_Bq[16 * 2048];

// ---------------- small float4 helpers ----------------------------------------
__device__ __forceinline__ float4 f4fma(float s, float4 h, float4 acc) {
    acc.x = fmaf(s, h.x, acc.x); acc.y = fmaf(s, h.y, acc.y);
    acc.z = fmaf(s, h.z, acc.z); acc.w = fmaf(s, h.w, acc.w);
    return acc;
}
__device__ __forceinline__ float4 f4scale(float4 a, float s) {
    return make_float4(a.x * s, a.y * s, a.z * s, a.w * s);
}

// ---------------- portable PTX helpers (sm_80-class; no 'a' features) ---------
__device__ __forceinline__ uint32_t smem_u32(const void* p) {
    uint32_t a;
    asm("{ .reg .u64 t; cvta.to.shared.u64 t, %1; cvt.u32.u64 %0, t; }" : "=r"(a) : "l"(p));
    return a;
}
__device__ __forceinline__ void ldsm_x4(uint32_t* r, uint32_t addr) {
    asm volatile("ldmatrix.sync.aligned.m8n8.x4.shared.b16 {%0,%1,%2,%3}, [%4];"
                 : "=r"(r[0]), "=r"(r[1]), "=r"(r[2]), "=r"(r[3]) : "r"(addr));
}
__device__ __forceinline__ void mma_f16(float* c, const uint32_t* a, const uint32_t* b) {
    asm volatile(
        "mma.sync.aligned.m16n8k16.row.col.f32.f16.f16.f32 "
        "{%0,%1,%2,%3}, {%4,%5,%6,%7}, {%8,%9}, {%0,%1,%2,%3};"
        : "+f"(c[0]), "+f"(c[1]), "+f"(c[2]), "+f"(c[3])
        : "r"(a[0]), "r"(a[1]), "r"(a[2]), "r"(a[3]), "r"(b[0]), "r"(b[1]));
}
#define CP_ASYNC16(dst, src) \
    asm volatile("cp.async.cg.shared.global [%0], [%1], 16;" :: "r"(dst), "l"(src))
#define CP_COMMIT() asm volatile("cp.async.commit_group;" ::: "memory")
#define CP_WAIT0()  asm volatile("cp.async.wait_group 0;" ::: "memory")

#define SWZ(x) ((x) ^ (((x) >> 3) & 0x70))

__device__ __forceinline__ float fast_tanh(float z) {
    const float ez = __expf(2.f * z);
    return 1.f - __fdividef(2.f, ez + 1.f);
}
__device__ __forceinline__ uint32_t h2pack(float a, float b) {
    const __half2 h = __floats2half2_rn(a, b);
    return *reinterpret_cast<const uint32_t*>(&h);
}

// ==============================================================================
// k_splitB: W1 [K=1024][N=256] fp32 -> fp16 n-major [n][k], 16 pre-swizzled
// 32KB K64-chunk images (row n = 64 fp16 = 128B).
// ==============================================================================
__global__ __launch_bounds__(256)
void k_splitB(const float* __restrict__ W1)
{
    const int p  = blockIdx.x * 256 + threadIdx.x;   // 0..131071
    const int n  = p & 255;
    const int kp = p >> 8;                           // 0..511
    const int k  = kp * 2;
    const int c  = k >> 6;                           // K64 chunk
    const int kk = k & 63;

    const float x0 = W1[(size_t)k * A_ + n];
    const float x1 = W1[(size_t)(k + 1) * A_ + n];
    char* img = reinterpret_cast<char*>(g_Bq) + (size_t)c * 32768;
    const uint32_t off = SWZ((uint32_t)n * 128 + (uint32_t)kk * 2);
    *reinterpret_cast<uint32_t*>(img + off) = h2pack(x0, x1);
}

// ==============================================================================
// k_scores_hmma: single-product fp16 GEMM via mma.sync.m16n8k16.f16.
// CTA tile 64(M) x 256(N, full), BK=64, 256 threads = 8 warps (2M x 4N),
// warp tile 32x64.  __launch_bounds__(256, 2): 2 CTAs/SM, one wave.
// (Frozen: best observed GEMM configuration, R10/R12.)
// ==============================================================================
#define OFF_V     0
#define OFF_B1    1024
#define OFF_DATA  4096
#define SB_OFF    8192       // B image within stage
#define STAGE_SZ  40960
#define SMEM_BYTES (OFF_DATA + 2 * STAGE_SZ)   // 86016

__global__ __launch_bounds__(256, 2)
void k_scores_hmma(const float* __restrict__ H, const float* __restrict__ b1,
                   const float* __restrict__ v)
{
    extern __shared__ char smem[];
    const uint32_t sb = smem_u32(smem);
    const int tid  = threadIdx.x;
    const int lane = tid & 31;
    const int wid  = tid >> 5;
    const int wm   = (wid & 1) * 32;       // warp M offset (0/32)
    const int wn   = (wid >> 1) * 64;      // warp N offset (0/64/128/192)
    const int m0   = blockIdx.x * 64;

    ((float*)(smem + OFF_V))[tid]  = v[tid];
    ((float*)(smem + OFF_B1))[tid] = b1[tid];

    // ---- A global load mapping: 64 rows x 64 floats, 16 floats per thread ----
    const int arow = tid >> 2;             // 0..63
    const int acol = (tid & 3) * 16;       // 0/16/32/48
    const float4* Ag = reinterpret_cast<const float4*>(H + (size_t)(m0 + arow) * D_ + acol);
    const uint32_t a_sts0 = SWZ((uint32_t)arow * 128 + (uint32_t)acol * 2);
    const uint32_t a_sts1 = SWZ((uint32_t)arow * 128 + (uint32_t)acol * 2 + 16);

    // ---- ldmatrix lane offsets (bytes within tile, pre-swizzle) ----
    uint32_t aoff[2];
#pragma unroll
    for (int mt = 0; mt < 2; mt++)
        aoff[mt] = (uint32_t)(wm + mt * 16 + (lane & 15)) * 128 + (uint32_t)(lane >> 4) * 16;
    const int bn = (lane & 7) + ((lane >> 4) << 3);
    const uint32_t b_kb = (uint32_t)((lane >> 3) & 1) * 16;
    uint32_t boff[4];
#pragma unroll
    for (int np = 0; np < 4; np++)
        boff[np] = (uint32_t)(wn + np * 16 + bn) * 128 + b_kb;

    float acc[2][8][4];
#pragma unroll
    for (int mt = 0; mt < 2; mt++)
#pragma unroll
        for (int nt = 0; nt < 8; nt++)
#pragma unroll
            for (int e = 0; e < 4; e++) acc[mt][nt][e] = 0.f;

    // load this thread's 16 A floats of chunk c and convert immediately
    auto loadA = [&](int c, uint4& q0, uint4& q1) {
        float4 x0 = __ldg(Ag + c * 16);
        float4 x1 = __ldg(Ag + c * 16 + 1);
        q0 = make_uint4(h2pack(x0.x, x0.y), h2pack(x0.z, x0.w),
                        h2pack(x1.x, x1.y), h2pack(x1.z, x1.w));
        x0 = __ldg(Ag + c * 16 + 2);
        x1 = __ldg(Ag + c * 16 + 3);
        q1 = make_uint4(h2pack(x0.x, x0.y), h2pack(x0.z, x0.w),
                        h2pack(x1.x, x1.y), h2pack(x1.z, x1.w));
    };

    // ---- prologue: fill stage 0 ----
    {
        const uint32_t st = sb + OFF_DATA;
#pragma unroll
        for (int u = 0; u < 8; u++)
            CP_ASYNC16(st + SB_OFF + (tid + u * 256) * 16, (const char*)(g_Bq + tid + u * 256));
        CP_COMMIT();
        uint4 q0, q1;
        loadA(0, q0, q1);
        *reinterpret_cast<uint4*>(smem + OFF_DATA + a_sts0) = q0;
        *reinterpret_cast<uint4*>(smem + OFF_DATA + a_sts1) = q1;
        CP_WAIT0();
        __syncthreads();
    }

#pragma unroll 1
    for (int c = 0; c < 16; c++) {
        const uint32_t cur = sb + OFF_DATA + (uint32_t)(c & 1) * STAGE_SZ;
        const uint32_t nxt = sb + OFF_DATA + (uint32_t)((c + 1) & 1) * STAGE_SZ;
        const bool more = (c + 1) < 16;

        uint4 q0, q1;
        if (more) {
#pragma unroll
            for (int u = 0; u < 8; u++)
                CP_ASYNC16(nxt + SB_OFF + (tid + u * 256) * 16,
                           (const char*)(g_Bq + (c + 1) * 2048 + tid + u * 256));
            CP_COMMIT();
            loadA(c + 1, q0, q1);
        }

        // ---- compute: 4 k16 steps per chunk (6 LDSM -> 16 HMMA each) ----
#pragma unroll
        for (int ks = 0; ks < 4; ks++) {
            uint32_t ah[2][4];
#pragma unroll
            for (int mt = 0; mt < 2; mt++)
                ldsm_x4(ah[mt], cur + SWZ(aoff[mt] + ks * 32));
            uint32_t bh[4][4];
#pragma unroll
            for (int np = 0; np < 4; np++)
                ldsm_x4(bh[np], cur + SB_OFF + SWZ(boff[np] + ks * 32));
#pragma unroll
            for (int mt = 0; mt < 2; mt++)
#pragma unroll
                for (int np = 0; np < 4; np++) {
                    mma_f16(acc[mt][np*2],   ah[mt], bh[np]);
                    mma_f16(acc[mt][np*2+1], ah[mt], bh[np] + 2);
                }
        }

        if (more) {
            const uint32_t nxt_off = OFF_DATA + (uint32_t)((c + 1) & 1) * STAGE_SZ;
            *reinterpret_cast<uint4*>(smem + nxt_off + a_sts0) = q0;
            *reinterpret_cast<uint4*>(smem + nxt_off + a_sts1) = q1;
            CP_WAIT0();
            __syncthreads();
        }
    }
    __syncthreads();   // stage area about to be reused as reduction buffer

    // ---- epilogue: s[m] = sum_n v[n] * tanh(acc + b1[n]) ----
    {
        const float* vs  = (const float*)(smem + OFF_V);
        const float* b1s = (const float*)(smem + OFF_B1);
        float* red = (float*)(smem + OFF_DATA);   // [64][4]
        const int nw = wid >> 1;

#pragma unroll
        for (int mt = 0; mt < 2; mt++) {
            float s0 = 0.f, s1 = 0.f;
#pragma unroll
            for (int nt = 0; nt < 8; nt++) {
#pragma unroll
                for (int e = 0; e < 2; e++) {
                    const int col = wn + nt * 8 + (lane & 3) * 2 + e;
                    s0 = fmaf(vs[col], fast_tanh(acc[mt][nt][e]     + b1s[col]), s0);
                    s1 = fmaf(vs[col], fast_tanh(acc[mt][nt][e + 2] + b1s[col]), s1);
                }
            }
            s0 += __shfl_xor_sync(0xffffffffu, s0, 1);
            s0 += __shfl_xor_sync(0xffffffffu, s0, 2);
            s1 += __shfl_xor_sync(0xffffffffu, s1, 1);
            s1 += __shfl_xor_sync(0xffffffffu, s1, 2);
            if ((lane & 3) == 0) {
                const int r0 = wm + mt * 16 + (lane >> 2);
                red[r0 * 4 + nw]       = s0;
                red[(r0 + 8) * 4 + nw] = s1;
            }
        }
        __syncthreads();
        if (tid < 64) {
            const float s = red[tid * 4] + red[tid * 4 + 1] + red[tid * 4 + 2] + red[tid * 4 + 3];
            g_s[m0 + tid] = s;
        }
    }
}

// ==============================================================================
// K2-prep: per batch b — max, w = exp(s - max), inclusive prefix (Zp) and
// inclusive suffix (Zs) scans of w. One block of 1024 threads per batch.
// ==============================================================================
__global__ __launch_bounds__(1024)
void k_prep()
{
    const int b = blockIdx.x;
    const int t = threadIdx.x;
    const int lane = t & 31;
    const int warp = t >> 5;

    __shared__ float sh[S_];
    __shared__ float red[32];
    __shared__ float bmax;

    const int base = b * S_;
    float s = g_s[base + t];

    float m = s;
#pragma unroll
    for (int off = 16; off > 0; off >>= 1)
        m = fmaxf(m, __shfl_xor_sync(0xffffffffu, m, off));
    if (lane == 0) red[warp] = m;
    __syncthreads();
    if (t == 0) {
        float mm = red[0];
        for (int i = 1; i < 32; i++) mm = fmaxf(mm, red[i]);
        bmax = mm;
    }
    __syncthreads();

    const float w = expf(s - bmax);
    g_w[base + t] = w;
    sh[t] = w;
    __syncthreads();

    float ps = w;
#pragma unroll
    for (int off = 1; off < 32; off <<= 1) {
        float n = __shfl_up_sync(0xffffffffu, ps, off);
        if (lane >= off) ps += n;
    }
    if (lane == 31) red[warp] = ps;
    __syncthreads();
    if (warp == 0) {
        float x = red[lane];
#pragma unroll
        for (int off = 1; off < 32; off <<= 1) {
            float n = __shfl_up_sync(0xffffffffu, x, off);
            if (lane >= off) x += n;
        }
        red[lane] = x;
    }
    __syncthreads();
    g_zp[base + t] = ps + (warp ? red[warp - 1] : 0.f);
    __syncthreads();

    float wr = sh[(S_ - 1) - t];
    float pr = wr;
#pragma unroll
    for (int off = 1; off < 32; off <<= 1) {
        float n = __shfl_up_sync(0xffffffffu, pr, off);
        if (lane >= off) pr += n;
    }
    if (lane == 31) red[warp] = pr;
    __syncthreads();
    if (warp == 0) {
        float x = red[lane];
#pragma unroll
        for (int off = 1; off < 32; off <<= 1) {
            float n = __shfl_up_sync(0xffffffffu, x, off);
            if (lane >= off) x += n;
        }
        red[lane] = x;
    }
    __syncthreads();
    g_zs[base + (S_ - 1) - t] = pr + (warp ? red[warp - 1] : 0.f);
}

// ==============================================================================
// K2-passA: segment partial sums  PS[b][seg][d] = sum_{l in seg} w[l]*h[b,l,d]
// Two segments per block: grid (B, NSEG/2), 256 threads, each thread runs TWO
// independent accumulator chains (seg 2s and 2s+1) with interleaved loads.
// ==============================================================================
__global__ __launch_bounds__(256)
void k_passA(const float* __restrict__ H)
{
    const int b  = blockIdx.x;
    const int sp = blockIdx.y;             // segment pair 0..31
    const int t  = threadIdx.x;
    const int d  = t * 4;

    __shared__ float ws[2 * SEGL];
    if (t < 2 * SEGL) ws[t] = g_w[b * S_ + sp * 2 * SEGL + t];
    __syncthreads();

    const float* hp = H + ((size_t)b * S_ + sp * 2 * SEGL) * D_ + d;
    float4 acc0 = make_float4(0.f, 0.f, 0.f, 0.f);
    float4 acc1 = make_float4(0.f, 0.f, 0.f, 0.f);
#pragma unroll
    for (int l = 0; l < SEGL; l++) {
        float4 h0 = *reinterpret_cast<const float4*>(hp + (size_t)l * D_);
        float4 h1 = *reinterpret_cast<const float4*>(hp + (size_t)(SEGL + l) * D_);
        acc0 = f4fma(ws[l], h0, acc0);
        acc1 = f4fma(ws[SEGL + l], h1, acc1);
    }
    float* pso = g_ps + ((size_t)b * NSEG + sp * 2) * D_ + d;
    *reinterpret_cast<float4*>(pso)      = acc0;
    *reinterpret_cast<float4*>(pso + D_) = acc1;
}

// ==============================================================================
// k_segscan: per (b,d) exclusive prefix AND suffix scans over segment partials
// + totals, fused into one kernel (partials register-cached).
// grid (B, 4) x 256 threads.
// ==============================================================================
__global__ __launch_bounds__(256)
void k_segscan()
{
    const int b = blockIdx.x;
    const int d = blockIdx.y * 256 + threadIdx.x;
    const size_t base = (size_t)b * NSEG * D_ + d;

    float vals[NSEG];
#pragma unroll
    for (int s = 0; s < NSEG; s++)
        vals[s] = g_ps[base + (size_t)s * D_];

    float run = 0.f;
#pragma unroll
    for (int s = 0; s < NSEG; s++) {
        g_cp[base + (size_t)s * D_] = run;
        run += vals[s];
    }
    g_tot[b * D_ + d] = run;

    run = 0.f;
#pragma unroll
    for (int s = NSEG - 1; s >= 0; s--) {
        g_cs[base + (size_t)s * D_] = run;
        run += vals[s];
    }
}

// ==============================================================================
// K2-passB: final pooled output (carries precomputed by k_segscan).
//  pt==0 (prefix):  out[j,d] = P_j[d]            / (Zp_j       * (j+1))
//  pt==1 (postfix): out[j,d] = Sfx_j[d]          / (Zs_j       * (S-j))
//  pt==2 (cloze):   out[j,d] = (T[d]-w_j h[j,d]) / ((Zt - w_j) * (S-1))
// ==============================================================================
__global__ __launch_bounds__(256)
void k_passB(const float* __restrict__ H, const int* __restrict__ pt_ids,
             float* __restrict__ out)
{
    const int b   = blockIdx.x;
    const int seg = blockIdx.y;
    const int t   = threadIdx.x;
    const int d   = t * 4;
    const int pt  = pt_ids[b];

    __shared__ float ws[SEGL], zps[SEGL], zss[SEGL];
    if (t < SEGL) {
        const int l = seg * SEGL + t;
        ws[t]  = g_w [b * S_ + l];
        zps[t] = g_zp[b * S_ + l];
        zss[t] = g_zs[b * S_ + l];
    }
    __syncthreads();

    const size_t cbase = ((size_t)b * NSEG + seg) * D_ + d;
    float4 carry;
    if (pt == 0)      carry = *reinterpret_cast<const float4*>(&g_cp[cbase]);
    else if (pt == 1) carry = *reinterpret_cast<const float4*>(&g_cs[cbase]);
    else              carry = *reinterpret_cast<const float4*>(&g_tot[b * D_ + d]);

    const float* hp = H   + ((size_t)b * S_ + seg * SEGL) * D_ + d;
    float*       op = out + ((size_t)b * S_ + seg * SEGL) * D_ + d;

    if (pt == 0) {
        float4 acc = carry;
#pragma unroll
        for (int i = 0; i < SEGL; i++) {
            const int j = seg * SEGL + i;
            float4 h4 = *reinterpret_cast<const float4*>(hp + (size_t)i * D_);
            acc = f4fma(ws[i], h4, acc);
            const float inv = 1.f / (zps[i] * (float)(j + 1));
            *reinterpret_cast<float4*>(op + (size_t)i * D_) = f4scale(acc, inv);
        }
    } else if (pt == 1) {
        float4 acc = carry;
#pragma unroll
        for (int i = SEGL - 1; i >= 0; i--) {
            const int j = seg * SEGL + i;
            float4 h4 = *reinterpret_cast<const float4*>(hp + (size_t)i * D_);
            acc = f4fma(ws[i], h4, acc);
            const float inv = 1.f / (zss[i] * (float)(S_ - j));
            *reinterpret_cast<float4*>(op + (size_t)i * D_) = f4scale(acc, inv);
        }
    } else {
        const float ztot = g_zp[b * S_ + (S_ - 1)];
        const float invcnt = 1.f / (float)(S_ - 1);
#pragma unroll
        for (int i = 0; i < SEGL; i++) {
            float4 h4 = *reinterpret_cast<const float4*>(hp + (size_t)i * D_);
            const float wl = ws[i];
            const float inv = invcnt / (ztot - wl);
            float4 num = f4fma(-wl, h4, carry);
            *reinterpret_cast<float4*>(op + (size_t)i * D_) = f4scale(num, inv);
        }
    }
}

// ==============================================================================
extern "C" void kernel_launch(void* const* d_in, const int* in_sizes, int n_in,
                              void* d_out, int out_size)
{
    const float* H   = (const float*)d_in[0];
    const float* W1  = (const float*)d_in[1];
    const float* b1  = (const float*)d_in[2];
    const float* v   = (const float*)d_in[3];
    const int*   pt  = (const int*)  d_in[4];
    float*       out = (float*)d_out;

    cudaFuncSetAttribute(k_scores_hmma, cudaFuncAttributeMaxDynamicSharedMemorySize, SMEM_BYTES);

    k_splitB     <<<512, 256>>>(W1);
    k_scores_hmma<<<(B_ * S_) / 64, 256, SMEM_BYTES>>>(H, b1, v);
    k_prep       <<<B_, S_>>>();
    k_passA      <<<dim3(B_, NSEG / 2), 256>>>(H);   // launch #4 -> profiled
    k_segscan    <<<dim3(B_, 4), 256>>>();
    k_passB      <<<dim3(B_, NSEG), 256>>>(H, pt, out);
}

// round 15
// speedup vs baseline: 1.1582x; 1.0272x over previous
#include <cuda_runtime.h>
#include <cuda_fp16.h>
#include <cstdint>

// Problem shape (fixed by dataset): B=16, S=1024, D=1024, A=256
#define B_    16
#define S_    1024
#define D_    1024
#define A_    256
#define NSEG  64
#define SEGL  16      // S_/NSEG

// ---------------- scratch (device globals; no allocation allowed) -------------
__device__ float g_s  [B_ * S_];             // final attention scores
__device__ float g_w  [B_ * S_];             // exp(s - max_b)
__device__ float g_zp [B_ * S_];             // inclusive prefix sum of w
__device__ float g_zs [B_ * S_];             // inclusive suffix sum of w
__device__ float g_ps [B_ * NSEG * D_];      // segment partial sums of w*h
__device__ float g_cp [B_ * NSEG * D_];      // exclusive prefix carries
__device__ float g_cs [B_ * NSEG * D_];      // exclusive suffix carries
__device__ float g_tot[B_ * D_];             // total sum of w*h
// fp16 W1, transposed (n-major), PRE-SWIZZLED: 16 K64-chunks x 32KB.
__device__ uint4 g_Bq[16 * 2048];

// ---------------- small float4 helpers ----------------------------------------
__device__ __forceinline__ float4 f4fma(float s, float4 h, float4 acc) {
    acc.x = fmaf(s, h.x, acc.x); acc.y = fmaf(s, h.y, acc.y);
    acc.z = fmaf(s, h.z, acc.z); acc.w = fmaf(s, h.w, acc.w);
    return acc;
}
__device__ __forceinline__ float4 f4scale(float4 a, float s) {
    return make_float4(a.x * s, a.y * s, a.z * s, a.w * s);
}
// streaming (evict-first) float4 store: written once, never re-read
__device__ __forceinline__ void st_cs4(float* p, float4 v) {
    asm volatile("st.global.cs.v4.f32 [%0], {%1, %2, %3, %4};"
                 :: "l"(p), "f"(v.x), "f"(v.y), "f"(v.z), "f"(v.w) : "memory");
}

// ---------------- portable PTX helpers (sm_80-class; no 'a' features) ---------
__device__ __forceinline__ uint32_t smem_u32(const void* p) {
    uint32_t a;
    asm("{ .reg .u64 t; cvta.to.shared.u64 t, %1; cvt.u32.u64 %0, t; }" : "=r"(a) : "l"(p));
    return a;
}
__device__ __forceinline__ void ldsm_x4(uint32_t* r, uint32_t addr) {
    asm volatile("ldmatrix.sync.aligned.m8n8.x4.shared.b16 {%0,%1,%2,%3}, [%4];"
                 : "=r"(r[0]), "=r"(r[1]), "=r"(r[2]), "=r"(r[3]) : "r"(addr));
}
__device__ __forceinline__ void mma_f16(float* c, const uint32_t* a, const uint32_t* b) {
    asm volatile(
        "mma.sync.aligned.m16n8k16.row.col.f32.f16.f16.f32 "
        "{%0,%1,%2,%3}, {%4,%5,%6,%7}, {%8,%9}, {%0,%1,%2,%3};"
        : "+f"(c[0]), "+f"(c[1]), "+f"(c[2]), "+f"(c[3])
        : "r"(a[0]), "r"(a[1]), "r"(a[2]), "r"(a[3]), "r"(b[0]), "r"(b[1]));
}
#define CP_ASYNC16(dst, src) \
    asm volatile("cp.async.cg.shared.global [%0], [%1], 16;" :: "r"(dst), "l"(src))
#define CP_COMMIT() asm volatile("cp.async.commit_group;" ::: "memory")
#define CP_WAIT0()  asm volatile("cp.async.wait_group 0;" ::: "memory")

#define SWZ(x) ((x) ^ (((x) >> 3) & 0x70))

__device__ __forceinline__ float fast_tanh(float z) {
    const float ez = __expf(2.f * z);
    return 1.f - __fdividef(2.f, ez + 1.f);
}
__device__ __forceinline__ uint32_t h2pack(float a, float b) {
    const __half2 h = __floats2half2_rn(a, b);
    return *reinterpret_cast<const uint32_t*>(&h);
}

// ==============================================================================
// k_splitB: W1 [K=1024][N=256] fp32 -> fp16 n-major [n][k], 16 pre-swizzled
// 32KB K64-chunk images (row n = 64 fp16 = 128B).
// ==============================================================================
__global__ __launch_bounds__(256)
void k_splitB(const float* __restrict__ W1)
{
    const int p  = blockIdx.x * 256 + threadIdx.x;   // 0..131071
    const int n  = p & 255;
    const int kp = p >> 8;                           // 0..511
    const int k  = kp * 2;
    const int c  = k >> 6;                           // K64 chunk
    const int kk = k & 63;

    const float x0 = W1[(size_t)k * A_ + n];
    const float x1 = W1[(size_t)(k + 1) * A_ + n];
    char* img = reinterpret_cast<char*>(g_Bq) + (size_t)c * 32768;
    const uint32_t off = SWZ((uint32_t)n * 128 + (uint32_t)kk * 2);
    *reinterpret_cast<uint32_t*>(img + off) = h2pack(x0, x1);
}

// ==============================================================================
// k_scores_hmma: single-product fp16 GEMM via mma.sync.m16n8k16.f16.
// CTA tile 64(M) x 256(N, full), BK=64, 256 threads = 8 warps (2M x 4N),
// warp tile 32x64.  __launch_bounds__(256, 2): 2 CTAs/SM, one wave.
// (Frozen: best observed GEMM configuration, R10/R12.)
// ==============================================================================
#define OFF_V     0
#define OFF_B1    1024
#define OFF_DATA  4096
#define SB_OFF    8192       // B image within stage
#define STAGE_SZ  40960
#define SMEM_BYTES (OFF_DATA + 2 * STAGE_SZ)   // 86016

__global__ __launch_bounds__(256, 2)
void k_scores_hmma(const float* __restrict__ H, const float* __restrict__ b1,
                   const float* __restrict__ v)
{
    extern __shared__ char smem[];
    const uint32_t sb = smem_u32(smem);
    const int tid  = threadIdx.x;
    const int lane = tid & 31;
    const int wid  = tid >> 5;
    const int wm   = (wid & 1) * 32;       // warp M offset (0/32)
    const int wn   = (wid >> 1) * 64;      // warp N offset (0/64/128/192)
    const int m0   = blockIdx.x * 64;

    ((float*)(smem + OFF_V))[tid]  = v[tid];
    ((float*)(smem + OFF_B1))[tid] = b1[tid];

    // ---- A global load mapping: 64 rows x 64 floats, 16 floats per thread ----
    const int arow = tid >> 2;             // 0..63
    const int acol = (tid & 3) * 16;       // 0/16/32/48
    const float4* Ag = reinterpret_cast<const float4*>(H + (size_t)(m0 + arow) * D_ + acol);
    const uint32_t a_sts0 = SWZ((uint32_t)arow * 128 + (uint32_t)acol * 2);
    const uint32_t a_sts1 = SWZ((uint32_t)arow * 128 + (uint32_t)acol * 2 + 16);

    // ---- ldmatrix lane offsets (bytes within tile, pre-swizzle) ----
    uint32_t aoff[2];
#pragma unroll
    for (int mt = 0; mt < 2; mt++)
        aoff[mt] = (uint32_t)(wm + mt * 16 + (lane & 15)) * 128 + (uint32_t)(lane >> 4) * 16;
    const int bn = (lane & 7) + ((lane >> 4) << 3);
    const uint32_t b_kb = (uint32_t)((lane >> 3) & 1) * 16;
    uint32_t boff[4];
#pragma unroll
    for (int np = 0; np < 4; np++)
        boff[np] = (uint32_t)(wn + np * 16 + bn) * 128 + b_kb;

    float acc[2][8][4];
#pragma unroll
    for (int mt = 0; mt < 2; mt++)
#pragma unroll
        for (int nt = 0; nt < 8; nt++)
#pragma unroll
            for (int e = 0; e < 4; e++) acc[mt][nt][e] = 0.f;

    // load this thread's 16 A floats of chunk c and convert immediately
    auto loadA = [&](int c, uint4& q0, uint4& q1) {
        float4 x0 = __ldg(Ag + c * 16);
        float4 x1 = __ldg(Ag + c * 16 + 1);
        q0 = make_uint4(h2pack(x0.x, x0.y), h2pack(x0.z, x0.w),
                        h2pack(x1.x, x1.y), h2pack(x1.z, x1.w));
        x0 = __ldg(Ag + c * 16 + 2);
        x1 = __ldg(Ag + c * 16 + 3);
        q1 = make_uint4(h2pack(x0.x, x0.y), h2pack(x0.z, x0.w),
                        h2pack(x1.x, x1.y), h2pack(x1.z, x1.w));
    };

    // ---- prologue: fill stage 0 ----
    {
        const uint32_t st = sb + OFF_DATA;
#pragma unroll
        for (int u = 0; u < 8; u++)
            CP_ASYNC16(st + SB_OFF + (tid + u * 256) * 16, (const char*)(g_Bq + tid + u * 256));
        CP_COMMIT();
        uint4 q0, q1;
        loadA(0, q0, q1);
        *reinterpret_cast<uint4*>(smem + OFF_DATA + a_sts0) = q0;
        *reinterpret_cast<uint4*>(smem + OFF_DATA + a_sts1) = q1;
        CP_WAIT0();
        __syncthreads();
    }

#pragma unroll 1
    for (int c = 0; c < 16; c++) {
        const uint32_t cur = sb + OFF_DATA + (uint32_t)(c & 1) * STAGE_SZ;
        const uint32_t nxt = sb + OFF_DATA + (uint32_t)((c + 1) & 1) * STAGE_SZ;
        const bool more = (c + 1) < 16;

        uint4 q0, q1;
        if (more) {
#pragma unroll
            for (int u = 0; u < 8; u++)
                CP_ASYNC16(nxt + SB_OFF + (tid + u * 256) * 16,
                           (const char*)(g_Bq + (c + 1) * 2048 + tid + u * 256));
            CP_COMMIT();
            loadA(c + 1, q0, q1);
        }

        // ---- compute: 4 k16 steps per chunk (6 LDSM -> 16 HMMA each) ----
#pragma unroll
        for (int ks = 0; ks < 4; ks++) {
            uint32_t ah[2][4];
#pragma unroll
            for (int mt = 0; mt < 2; mt++)
                ldsm_x4(ah[mt], cur + SWZ(aoff[mt] + ks * 32));
            uint32_t bh[4][4];
#pragma unroll
            for (int np = 0; np < 4; np++)
                ldsm_x4(bh[np], cur + SB_OFF + SWZ(boff[np] + ks * 32));
#pragma unroll
            for (int mt = 0; mt < 2; mt++)
#pragma unroll
                for (int np = 0; np < 4; np++) {
                    mma_f16(acc[mt][np*2],   ah[mt], bh[np]);
                    mma_f16(acc[mt][np*2+1], ah[mt], bh[np] + 2);
                }
        }

        if (more) {
            const uint32_t nxt_off = OFF_DATA + (uint32_t)((c + 1) & 1) * STAGE_SZ;
            *reinterpret_cast<uint4*>(smem + nxt_off + a_sts0) = q0;
            *reinterpret_cast<uint4*>(smem + nxt_off + a_sts1) = q1;
            CP_WAIT0();
            __syncthreads();
        }
    }
    __syncthreads();   // stage area about to be reused as reduction buffer

    // ---- epilogue: s[m] = sum_n v[n] * tanh(acc + b1[n]) ----
    {
        const float* vs  = (const float*)(smem + OFF_V);
        const float* b1s = (const float*)(smem + OFF_B1);
        float* red = (float*)(smem + OFF_DATA);   // [64][4]
        const int nw = wid >> 1;

#pragma unroll
        for (int mt = 0; mt < 2; mt++) {
            float s0 = 0.f, s1 = 0.f;
#pragma unroll
            for (int nt = 0; nt < 8; nt++) {
#pragma unroll
                for (int e = 0; e < 2; e++) {
                    const int col = wn + nt * 8 + (lane & 3) * 2 + e;
                    s0 = fmaf(vs[col], fast_tanh(acc[mt][nt][e]     + b1s[col]), s0);
                    s1 = fmaf(vs[col], fast_tanh(acc[mt][nt][e + 2] + b1s[col]), s1);
                }
            }
            s0 += __shfl_xor_sync(0xffffffffu, s0, 1);
            s0 += __shfl_xor_sync(0xffffffffu, s0, 2);
            s1 += __shfl_xor_sync(0xffffffffu, s1, 1);
            s1 += __shfl_xor_sync(0xffffffffu, s1, 2);
            if ((lane & 3) == 0) {
                const int r0 = wm + mt * 16 + (lane >> 2);
                red[r0 * 4 + nw]       = s0;
                red[(r0 + 8) * 4 + nw] = s1;
            }
        }
        __syncthreads();
        if (tid < 64) {
            const float s = red[tid * 4] + red[tid * 4 + 1] + red[tid * 4 + 2] + red[tid * 4 + 3];
            g_s[m0 + tid] = s;
        }
    }
}

// ==============================================================================
// K2-prep: per batch b — max, w = exp(s - max), inclusive prefix (Zp) and
// inclusive suffix (Zs) scans of w. One block of 1024 threads per batch.
// ==============================================================================
__global__ __launch_bounds__(1024)
void k_prep()
{
    const int b = blockIdx.x;
    const int t = threadIdx.x;
    const int lane = t & 31;
    const int warp = t >> 5;

    __shared__ float sh[S_];
    __shared__ float red[32];
    __shared__ float bmax;

    const int base = b * S_;
    float s = g_s[base + t];

    float m = s;
#pragma unroll
    for (int off = 16; off > 0; off >>= 1)
        m = fmaxf(m, __shfl_xor_sync(0xffffffffu, m, off));
    if (lane == 0) red[warp] = m;
    __syncthreads();
    if (t == 0) {
        float mm = red[0];
        for (int i = 1; i < 32; i++) mm = fmaxf(mm, red[i]);
        bmax = mm;
    }
    __syncthreads();

    const float w = expf(s - bmax);
    g_w[base + t] = w;
    sh[t] = w;
    __syncthreads();

    float ps = w;
#pragma unroll
    for (int off = 1; off < 32; off <<= 1) {
        float n = __shfl_up_sync(0xffffffffu, ps, off);
        if (lane >= off) ps += n;
    }
    if (lane == 31) red[warp] = ps;
    __syncthreads();
    if (warp == 0) {
        float x = red[lane];
#pragma unroll
        for (int off = 1; off < 32; off <<= 1) {
            float n = __shfl_up_sync(0xffffffffu, x, off);
            if (lane >= off) x += n;
        }
        red[lane] = x;
    }
    __syncthreads();
    g_zp[base + t] = ps + (warp ? red[warp - 1] : 0.f);
    __syncthreads();

    float wr = sh[(S_ - 1) - t];
    float pr = wr;
#pragma unroll
    for (int off = 1; off < 32; off <<= 1) {
        float n = __shfl_up_sync(0xffffffffu, pr, off);
        if (lane >= off) pr += n;
    }
    if (lane == 31) red[warp] = pr;
    __syncthreads();
    if (warp == 0) {
        float x = red[lane];
#pragma unroll
        for (int off = 1; off < 32; off <<= 1) {
            float n = __shfl_up_sync(0xffffffffu, x, off);
            if (lane >= off) x += n;
        }
        red[lane] = x;
    }
    __syncthreads();
    g_zs[base + (S_ - 1) - t] = pr + (warp ? red[warp - 1] : 0.f);
}

// ==============================================================================
// K2-passA: segment partial sums  PS[b][seg][d] = sum_{l in seg} w[l]*h[b,l,d]
// (R12 champion config: grid (B, NSEG), 256 threads, float4 over D.)
// ==============================================================================
__global__ __launch_bounds__(256)
void k_passA(const float* __restrict__ H)
{
    const int b   = blockIdx.x;
    const int seg = blockIdx.y;
    const int t   = threadIdx.x;
    const int d   = t * 4;

    __shared__ float ws[SEGL];
    if (t < SEGL) ws[t] = g_w[b * S_ + seg * SEGL + t];
    __syncthreads();

    const float4* hp = reinterpret_cast<const float4*>(H + ((size_t)b * S_ + seg * SEGL) * D_ + d);
    float4 acc = make_float4(0.f, 0.f, 0.f, 0.f);
#pragma unroll
    for (int l = 0; l < SEGL; l++) {
        float4 h4 = __ldg(hp + (size_t)l * (D_ / 4));
        acc = f4fma(ws[l], h4, acc);
    }
    *reinterpret_cast<float4*>(&g_ps[((size_t)b * NSEG + seg) * D_ + d]) = acc;
}

// ==============================================================================
// k_segscan: per (b,d) exclusive prefix AND suffix scans over segment partials
// + totals, fused into one kernel (partials register-cached).
// grid (B, 4) x 256 threads.  (R12 champion config.)
// ==============================================================================
__global__ __launch_bounds__(256)
void k_segscan()
{
    const int b = blockIdx.x;
    const int d = blockIdx.y * 256 + threadIdx.x;
    const size_t base = (size_t)b * NSEG * D_ + d;

    float vals[NSEG];
#pragma unroll
    for (int s = 0; s < NSEG; s++)
        vals[s] = g_ps[base + (size_t)s * D_];

    float run = 0.f;
#pragma unroll
    for (int s = 0; s < NSEG; s++) {
        g_cp[base + (size_t)s * D_] = run;
        run += vals[s];
    }
    g_tot[b * D_ + d] = run;

    run = 0.f;
#pragma unroll
    for (int s = NSEG - 1; s >= 0; s--) {
        g_cs[base + (size_t)s * D_] = run;
        run += vals[s];
    }
}

// ==============================================================================
// K2-passB: final pooled output (carries precomputed by k_segscan).
//  pt==0 (prefix):  out[j,d] = P_j[d]            / (Zp_j       * (j+1))
//  pt==1 (postfix): out[j,d] = Sfx_j[d]          / (Zs_j       * (S-j))
//  pt==2 (cloze):   out[j,d] = (T[d]-w_j h[j,d]) / ((Zt - w_j) * (S-1))
// Output written with streaming stores (never re-read -> keep L2 for H/carries).
// ==============================================================================
__global__ __launch_bounds__(256)
void k_passB(const float* __restrict__ H, const int* __restrict__ pt_ids,
             float* __restrict__ out)
{
    const int b   = blockIdx.x;
    const int seg = blockIdx.y;
    const int t   = threadIdx.x;
    const int d   = t * 4;
    const int pt  = pt_ids[b];

    __shared__ float ws[SEGL], zps[SEGL], zss[SEGL];
    if (t < SEGL) {
        const int l = seg * SEGL + t;
        ws[t]  = g_w [b * S_ + l];
        zps[t] = g_zp[b * S_ + l];
        zss[t] = g_zs[b * S_ + l];
    }
    __syncthreads();

    const size_t cbase = ((size_t)b * NSEG + seg) * D_ + d;
    float4 carry;
    if (pt == 0)      carry = __ldg(reinterpret_cast<const float4*>(&g_cp[cbase]));
    else if (pt == 1) carry = __ldg(reinterpret_cast<const float4*>(&g_cs[cbase]));
    else              carry = __ldg(reinterpret_cast<const float4*>(&g_tot[b * D_ + d]));

    const float4* hp = reinterpret_cast<const float4*>(H + ((size_t)b * S_ + seg * SEGL) * D_ + d);
    float*        op = out + ((size_t)b * S_ + seg * SEGL) * D_ + d;

    if (pt == 0) {
        float4 acc = carry;
#pragma unroll
        for (int i = 0; i < SEGL; i++) {
            const int j = seg * SEGL + i;
            float4 h4 = __ldg(hp + (size_t)i * (D_ / 4));
            acc = f4fma(ws[i], h4, acc);
            const float inv = 1.f / (zps[i] * (float)(j + 1));
            st_cs4(op + (size_t)i * D_, f4scale(acc, inv));
        }
    } else if (pt == 1) {
        float4 acc = carry;
#pragma unroll
        for (int i = SEGL - 1; i >= 0; i--) {
            const int j = seg * SEGL + i;
            float4 h4 = __ldg(hp + (size_t)i * (D_ / 4));
            acc = f4fma(ws[i], h4, acc);
            const float inv = 1.f / (zss[i] * (float)(S_ - j));
            st_cs4(op + (size_t)i * D_, f4scale(acc, inv));
        }
    } else {
        const float ztot = g_zp[b * S_ + (S_ - 1)];
        const float invcnt = 1.f / (float)(S_ - 1);
#pragma unroll
        for (int i = 0; i < SEGL; i++) {
            float4 h4 = __ldg(hp + (size_t)i * (D_ / 4));
            const float wl = ws[i];
            const float inv = invcnt / (ztot - wl);
            float4 num = f4fma(-wl, h4, carry);
            st_cs4(op + (size_t)i * D_, f4scale(num, inv));
        }
    }
}

// ==============================================================================
extern "C" void kernel_launch(void* const* d_in, const int* in_sizes, int n_in,
                              void* d_out, int out_size)
{
    const float* H   = (const float*)d_in[0];
    const float* W1  = (const float*)d_in[1];
    const float* b1  = (const float*)d_in[2];
    const float* v   = (const float*)d_in[3];
    const int*   pt  = (const int*)  d_in[4];
    float*       out = (float*)d_out;

    cudaFuncSetAttribute(k_scores_hmma, cudaFuncAttributeMaxDynamicSharedMemorySize, SMEM_BYTES);

    k_splitB     <<<512, 256>>>(W1);
    k_scores_hmma<<<(B_ * S_) / 64, 256, SMEM_BYTES>>>(H, b1, v);
    k_prep       <<<B_, S_>>>();
    k_passA      <<<dim3(B_, NSEG), 256>>>(H);      // launch #4 -> profiled
    k_segscan    <<<dim3(B_, 4), 256>>>();
    k_passB      <<<dim3(B_, NSEG), 256>>>(H, pt, out);
}

// round 16
// speedup vs baseline: 1.1936x; 1.0306x over previous
#include <cuda_runtime.h>
#include <cuda_fp16.h>
#include <cstdint>

// Problem shape (fixed by dataset): B=16, S=1024, D=1024, A=256
#define B_    16
#define S_    1024
#define D_    1024
#define A_    256
#define NSEG  64
#define SEGL  16      // S_/NSEG

// ---------------- scratch (device globals; no allocation allowed) -------------
__device__ float g_s  [B_ * S_];             // final attention scores
__device__ float g_w  [B_ * S_];             // exp(s - max_b)
__device__ float g_zp [B_ * S_];             // inclusive prefix sum of w
__device__ float g_zs [B_ * S_];             // inclusive suffix sum of w
__device__ float g_ps [B_ * NSEG * D_];      // segment partial sums of w*h
__device__ float g_cp [B_ * NSEG * D_];      // exclusive prefix carries
__device__ float g_cs [B_ * NSEG * D_];      // exclusive suffix carries
__device__ float g_tot[B_ * D_];             // total sum of w*h
__device__ __half g_Hh[(size_t)B_ * S_ * D_]; // fp16 mirror of H (written by GEMM)
// fp16 W1, transposed (n-major), PRE-SWIZZLED: 16 K64-chunks x 32KB.
__device__ uint4 g_Bq[16 * 2048];

// ---------------- small float4 helpers ----------------------------------------
__device__ __forceinline__ float4 f4fma(float s, float4 h, float4 acc) {
    acc.x = fmaf(s, h.x, acc.x); acc.y = fmaf(s, h.y, acc.y);
    acc.z = fmaf(s, h.z, acc.z); acc.w = fmaf(s, h.w, acc.w);
    return acc;
}
__device__ __forceinline__ float4 f4scale(float4 a, float s) {
    return make_float4(a.x * s, a.y * s, a.z * s, a.w * s);
}
// streaming (evict-first) float4 store: written once, never re-read
__device__ __forceinline__ void st_cs4(float* p, float4 v) {
    asm volatile("st.global.cs.v4.f32 [%0], {%1, %2, %3, %4};"
                 :: "l"(p), "f"(v.x), "f"(v.y), "f"(v.z), "f"(v.w) : "memory");
}
// unpack 4 fp16 (as uint2) -> float4
__device__ __forceinline__ float4 h4tof4(uint2 r) {
    const __half2 h01 = *reinterpret_cast<__half2*>(&r.x);
    const __half2 h23 = *reinterpret_cast<__half2*>(&r.y);
    const float2 f01 = __half22float2(h01);
    const float2 f23 = __half22float2(h23);
    return make_float4(f01.x, f01.y, f23.x, f23.y);
}

// ---------------- portable PTX helpers (sm_80-class; no 'a' features) ---------
__device__ __forceinline__ uint32_t smem_u32(const void* p) {
    uint32_t a;
    asm("{ .reg .u64 t; cvta.to.shared.u64 t, %1; cvt.u32.u64 %0, t; }" : "=r"(a) : "l"(p));
    return a;
}
__device__ __forceinline__ void ldsm_x4(uint32_t* r, uint32_t addr) {
    asm volatile("ldmatrix.sync.aligned.m8n8.x4.shared.b16 {%0,%1,%2,%3}, [%4];"
                 : "=r"(r[0]), "=r"(r[1]), "=r"(r[2]), "=r"(r[3]) : "r"(addr));
}
__device__ __forceinline__ void mma_f16(float* c, const uint32_t* a, const uint32_t* b) {
    asm volatile(
        "mma.sync.aligned.m16n8k16.row.col.f32.f16.f16.f32 "
        "{%0,%1,%2,%3}, {%4,%5,%6,%7}, {%8,%9}, {%0,%1,%2,%3};"
        : "+f"(c[0]), "+f"(c[1]), "+f"(c[2]), "+f"(c[3])
        : "r"(a[0]), "r"(a[1]), "r"(a[2]), "r"(a[3]), "r"(b[0]), "r"(b[1]));
}
#define CP_ASYNC16(dst, src) \
    asm volatile("cp.async.cg.shared.global [%0], [%1], 16;" :: "r"(dst), "l"(src))
#define CP_COMMIT() asm volatile("cp.async.commit_group;" ::: "memory")
#define CP_WAIT0()  asm volatile("cp.async.wait_group 0;" ::: "memory")

#define SWZ(x) ((x) ^ (((x) >> 3) & 0x70))

__device__ __forceinline__ float fast_tanh(float z) {
    const float ez = __expf(2.f * z);
    return 1.f - __fdividef(2.f, ez + 1.f);
}
__device__ __forceinline__ uint32_t h2pack(float a, float b) {
    const __half2 h = __floats2half2_rn(a, b);
    return *reinterpret_cast<const uint32_t*>(&h);
}

// ==============================================================================
// k_splitB: W1 [K=1024][N=256] fp32 -> fp16 n-major [n][k], 16 pre-swizzled
// 32KB K64-chunk images (row n = 64 fp16 = 128B).
// ==============================================================================
__global__ __launch_bounds__(256)
void k_splitB(const float* __restrict__ W1)
{
    const int p  = blockIdx.x * 256 + threadIdx.x;   // 0..131071
    const int n  = p & 255;
    const int kp = p >> 8;                           // 0..511
    const int k  = kp * 2;
    const int c  = k >> 6;                           // K64 chunk
    const int kk = k & 63;

    const float x0 = W1[(size_t)k * A_ + n];
    const float x1 = W1[(size_t)(k + 1) * A_ + n];
    char* img = reinterpret_cast<char*>(g_Bq) + (size_t)c * 32768;
    const uint32_t off = SWZ((uint32_t)n * 128 + (uint32_t)kk * 2);
    *reinterpret_cast<uint32_t*>(img + off) = h2pack(x0, x1);
}

// ==============================================================================
// k_scores_hmma: single-product fp16 GEMM via mma.sync.m16n8k16.f16.
// CTA tile 64(M) x 256(N, full), BK=64, 256 threads = 8 warps (2M x 4N),
// warp tile 32x64.  __launch_bounds__(256, 2): 2 CTAs/SM, one wave.
// NEW: the converted fp16 A tiles are ALSO persisted to g_Hh (fp16 mirror of
// H, 32MB) so passA/passB read half the bytes.
// ==============================================================================
#define OFF_V     0
#define OFF_B1    1024
#define OFF_DATA  4096
#define SB_OFF    8192       // B image within stage
#define STAGE_SZ  40960
#define SMEM_BYTES (OFF_DATA + 2 * STAGE_SZ)   // 86016

__global__ __launch_bounds__(256, 2)
void k_scores_hmma(const float* __restrict__ H, const float* __restrict__ b1,
                   const float* __restrict__ v)
{
    extern __shared__ char smem[];
    const uint32_t sb = smem_u32(smem);
    const int tid  = threadIdx.x;
    const int lane = tid & 31;
    const int wid  = tid >> 5;
    const int wm   = (wid & 1) * 32;       // warp M offset (0/32)
    const int wn   = (wid >> 1) * 64;      // warp N offset (0/64/128/192)
    const int m0   = blockIdx.x * 64;

    ((float*)(smem + OFF_V))[tid]  = v[tid];
    ((float*)(smem + OFF_B1))[tid] = b1[tid];

    // ---- A global load mapping: 64 rows x 64 floats, 16 floats per thread ----
    const int arow = tid >> 2;             // 0..63
    const int acol = (tid & 3) * 16;       // 0/16/32/48
    const float4* Ag = reinterpret_cast<const float4*>(H + (size_t)(m0 + arow) * D_ + acol);
    __half* Hh = g_Hh + (size_t)(m0 + arow) * D_ + acol;
    const uint32_t a_sts0 = SWZ((uint32_t)arow * 128 + (uint32_t)acol * 2);
    const uint32_t a_sts1 = SWZ((uint32_t)arow * 128 + (uint32_t)acol * 2 + 16);

    // ---- ldmatrix lane offsets (bytes within tile, pre-swizzle) ----
    uint32_t aoff[2];
#pragma unroll
    for (int mt = 0; mt < 2; mt++)
        aoff[mt] = (uint32_t)(wm + mt * 16 + (lane & 15)) * 128 + (uint32_t)(lane >> 4) * 16;
    const int bn = (lane & 7) + ((lane >> 4) << 3);
    const uint32_t b_kb = (uint32_t)((lane >> 3) & 1) * 16;
    uint32_t boff[4];
#pragma unroll
    for (int np = 0; np < 4; np++)
        boff[np] = (uint32_t)(wn + np * 16 + bn) * 128 + b_kb;

    float acc[2][8][4];
#pragma unroll
    for (int mt = 0; mt < 2; mt++)
#pragma unroll
        for (int nt = 0; nt < 8; nt++)
#pragma unroll
            for (int e = 0; e < 4; e++) acc[mt][nt][e] = 0.f;

    // load this thread's 16 A floats of chunk c, convert, and mirror to g_Hh
    auto loadA = [&](int c, uint4& q0, uint4& q1) {
        float4 x0 = __ldg(Ag + c * 16);
        float4 x1 = __ldg(Ag + c * 16 + 1);
        q0 = make_uint4(h2pack(x0.x, x0.y), h2pack(x0.z, x0.w),
                        h2pack(x1.x, x1.y), h2pack(x1.z, x1.w));
        x0 = __ldg(Ag + c * 16 + 2);
        x1 = __ldg(Ag + c * 16 + 3);
        q1 = make_uint4(h2pack(x0.x, x0.y), h2pack(x0.z, x0.w),
                        h2pack(x1.x, x1.y), h2pack(x1.z, x1.w));
        uint4* dst = reinterpret_cast<uint4*>(Hh + c * 64);
        dst[0] = q0;
        dst[1] = q1;
    };

    // ---- prologue: fill stage 0 ----
    {
        const uint32_t st = sb + OFF_DATA;
#pragma unroll
        for (int u = 0; u < 8; u++)
            CP_ASYNC16(st + SB_OFF + (tid + u * 256) * 16, (const char*)(g_Bq + tid + u * 256));
        CP_COMMIT();
        uint4 q0, q1;
        loadA(0, q0, q1);
        *reinterpret_cast<uint4*>(smem + OFF_DATA + a_sts0) = q0;
        *reinterpret_cast<uint4*>(smem + OFF_DATA + a_sts1) = q1;
        CP_WAIT0();
        __syncthreads();
    }

#pragma unroll 1
    for (int c = 0; c < 16; c++) {
        const uint32_t cur = sb + OFF_DATA + (uint32_t)(c & 1) * STAGE_SZ;
        const uint32_t nxt = sb + OFF_DATA + (uint32_t)((c + 1) & 1) * STAGE_SZ;
        const bool more = (c + 1) < 16;

        uint4 q0, q1;
        if (more) {
#pragma unroll
            for (int u = 0; u < 8; u++)
                CP_ASYNC16(nxt + SB_OFF + (tid + u * 256) * 16,
                           (const char*)(g_Bq + (c + 1) * 2048 + tid + u * 256));
            CP_COMMIT();
            loadA(c + 1, q0, q1);
        }

        // ---- compute: 4 k16 steps per chunk (6 LDSM -> 16 HMMA each) ----
#pragma unroll
        for (int ks = 0; ks < 4; ks++) {
            uint32_t ah[2][4];
#pragma unroll
            for (int mt = 0; mt < 2; mt++)
                ldsm_x4(ah[mt], cur + SWZ(aoff[mt] + ks * 32));
            uint32_t bh[4][4];
#pragma unroll
            for (int np = 0; np < 4; np++)
                ldsm_x4(bh[np], cur + SB_OFF + SWZ(boff[np] + ks * 32));
#pragma unroll
            for (int mt = 0; mt < 2; mt++)
#pragma unroll
                for (int np = 0; np < 4; np++) {
                    mma_f16(acc[mt][np*2],   ah[mt], bh[np]);
                    mma_f16(acc[mt][np*2+1], ah[mt], bh[np] + 2);
                }
        }

        if (more) {
            const uint32_t nxt_off = OFF_DATA + (uint32_t)((c + 1) & 1) * STAGE_SZ;
            *reinterpret_cast<uint4*>(smem + nxt_off + a_sts0) = q0;
            *reinterpret_cast<uint4*>(smem + nxt_off + a_sts1) = q1;
            CP_WAIT0();
            __syncthreads();
        }
    }
    __syncthreads();   // stage area about to be reused as reduction buffer

    // ---- epilogue: s[m] = sum_n v[n] * tanh(acc + b1[n]) ----
    {
        const float* vs  = (const float*)(smem + OFF_V);
        const float* b1s = (const float*)(smem + OFF_B1);
        float* red = (float*)(smem + OFF_DATA);   // [64][4]
        const int nw = wid >> 1;

#pragma unroll
        for (int mt = 0; mt < 2; mt++) {
            float s0 = 0.f, s1 = 0.f;
#pragma unroll
            for (int nt = 0; nt < 8; nt++) {
#pragma unroll
                for (int e = 0; e < 2; e++) {
                    const int col = wn + nt * 8 + (lane & 3) * 2 + e;
                    s0 = fmaf(vs[col], fast_tanh(acc[mt][nt][e]     + b1s[col]), s0);
                    s1 = fmaf(vs[col], fast_tanh(acc[mt][nt][e + 2] + b1s[col]), s1);
                }
            }
            s0 += __shfl_xor_sync(0xffffffffu, s0, 1);
            s0 += __shfl_xor_sync(0xffffffffu, s0, 2);
            s1 += __shfl_xor_sync(0xffffffffu, s1, 1);
            s1 += __shfl_xor_sync(0xffffffffu, s1, 2);
            if ((lane & 3) == 0) {
                const int r0 = wm + mt * 16 + (lane >> 2);
                red[r0 * 4 + nw]       = s0;
                red[(r0 + 8) * 4 + nw] = s1;
            }
        }
        __syncthreads();
        if (tid < 64) {
            const float s = red[tid * 4] + red[tid * 4 + 1] + red[tid * 4 + 2] + red[tid * 4 + 3];
            g_s[m0 + tid] = s;
        }
    }
}

// ==============================================================================
// K2-prep: per batch b — max, w = exp(s - max), inclusive prefix (Zp) and
// inclusive suffix (Zs) scans of w. One block of 1024 threads per batch.
// ==============================================================================
__global__ __launch_bounds__(1024)
void k_prep()
{
    const int b = blockIdx.x;
    const int t = threadIdx.x;
    const int lane = t & 31;
    const int warp = t >> 5;

    __shared__ float sh[S_];
    __shared__ float red[32];
    __shared__ float bmax;

    const int base = b * S_;
    float s = g_s[base + t];

    float m = s;
#pragma unroll
    for (int off = 16; off > 0; off >>= 1)
        m = fmaxf(m, __shfl_xor_sync(0xffffffffu, m, off));
    if (lane == 0) red[warp] = m;
    __syncthreads();
    if (t == 0) {
        float mm = red[0];
        for (int i = 1; i < 32; i++) mm = fmaxf(mm, red[i]);
        bmax = mm;
    }
    __syncthreads();

    const float w = expf(s - bmax);
    g_w[base + t] = w;
    sh[t] = w;
    __syncthreads();

    float ps = w;
#pragma unroll
    for (int off = 1; off < 32; off <<= 1) {
        float n = __shfl_up_sync(0xffffffffu, ps, off);
        if (lane >= off) ps += n;
    }
    if (lane == 31) red[warp] = ps;
    __syncthreads();
    if (warp == 0) {
        float x = red[lane];
#pragma unroll
        for (int off = 1; off < 32; off <<= 1) {
            float n = __shfl_up_sync(0xffffffffu, x, off);
            if (lane >= off) x += n;
        }
        red[lane] = x;
    }
    __syncthreads();
    g_zp[base + t] = ps + (warp ? red[warp - 1] : 0.f);
    __syncthreads();

    float wr = sh[(S_ - 1) - t];
    float pr = wr;
#pragma unroll
    for (int off = 1; off < 32; off <<= 1) {
        float n = __shfl_up_sync(0xffffffffu, pr, off);
        if (lane >= off) pr += n;
    }
    if (lane == 31) red[warp] = pr;
    __syncthreads();
    if (warp == 0) {
        float x = red[lane];
#pragma unroll
        for (int off = 1; off < 32; off <<= 1) {
            float n = __shfl_up_sync(0xffffffffu, x, off);
            if (lane >= off) x += n;
        }
        red[lane] = x;
    }
    __syncthreads();
    g_zs[base + (S_ - 1) - t] = pr + (warp ? red[warp - 1] : 0.f);
}

// ==============================================================================
// K2-passA: segment partial sums  PS[b][seg][d] = sum_{l in seg} w[l]*h[b,l,d]
// Reads the fp16 mirror g_Hh (half the bytes of fp32 H).
// ==============================================================================
__global__ __launch_bounds__(256)
void k_passA()
{
    const int b   = blockIdx.x;
    const int seg = blockIdx.y;
    const int t   = threadIdx.x;
    const int d   = t * 4;

    __shared__ float ws[SEGL];
    if (t < SEGL) ws[t] = g_w[b * S_ + seg * SEGL + t];
    __syncthreads();

    const uint2* hp = reinterpret_cast<const uint2*>(
        g_Hh + ((size_t)b * S_ + seg * SEGL) * D_ + d);
    float4 acc = make_float4(0.f, 0.f, 0.f, 0.f);
#pragma unroll
    for (int l = 0; l < SEGL; l++) {
        float4 h4 = h4tof4(__ldg(hp + (size_t)l * (D_ / 4)));
        acc = f4fma(ws[l], h4, acc);
    }
    *reinterpret_cast<float4*>(&g_ps[((size_t)b * NSEG + seg) * D_ + d]) = acc;
}

// ==============================================================================
// k_segscan: per (b,d) exclusive prefix AND suffix scans over segment partials
// + totals, fused into one kernel (partials register-cached).
// grid (B, 4) x 256 threads.
// ==============================================================================
__global__ __launch_bounds__(256)
void k_segscan()
{
    const int b = blockIdx.x;
    const int d = blockIdx.y * 256 + threadIdx.x;
    const size_t base = (size_t)b * NSEG * D_ + d;

    float vals[NSEG];
#pragma unroll
    for (int s = 0; s < NSEG; s++)
        vals[s] = g_ps[base + (size_t)s * D_];

    float run = 0.f;
#pragma unroll
    for (int s = 0; s < NSEG; s++) {
        g_cp[base + (size_t)s * D_] = run;
        run += vals[s];
    }
    g_tot[b * D_ + d] = run;

    run = 0.f;
#pragma unroll
    for (int s = NSEG - 1; s >= 0; s--) {
        g_cs[base + (size_t)s * D_] = run;
        run += vals[s];
    }
}

// ==============================================================================
// K2-passB: final pooled output (carries precomputed by k_segscan).
//  pt==0 (prefix):  out[j,d] = P_j[d]            / (Zp_j       * (j+1))
//  pt==1 (postfix): out[j,d] = Sfx_j[d]          / (Zs_j       * (S-j))
//  pt==2 (cloze):   out[j,d] = (T[d]-w_j h[j,d]) / ((Zt - w_j) * (S-1))
// Reads fp16 mirror g_Hh; output via streaming stores.
// ==============================================================================
__global__ __launch_bounds__(256)
void k_passB(const int* __restrict__ pt_ids, float* __restrict__ out)
{
    const int b   = blockIdx.x;
    const int seg = blockIdx.y;
    const int t   = threadIdx.x;
    const int d   = t * 4;
    const int pt  = pt_ids[b];

    __shared__ float ws[SEGL], zps[SEGL], zss[SEGL];
    if (t < SEGL) {
        const int l = seg * SEGL + t;
        ws[t]  = g_w [b * S_ + l];
        zps[t] = g_zp[b * S_ + l];
        zss[t] = g_zs[b * S_ + l];
    }
    __syncthreads();

    const size_t cbase = ((size_t)b * NSEG + seg) * D_ + d;
    float4 carry;
    if (pt == 0)      carry = __ldg(reinterpret_cast<const float4*>(&g_cp[cbase]));
    else if (pt == 1) carry = __ldg(reinterpret_cast<const float4*>(&g_cs[cbase]));
    else              carry = __ldg(reinterpret_cast<const float4*>(&g_tot[b * D_ + d]));

    const uint2* hp = reinterpret_cast<const uint2*>(
        g_Hh + ((size_t)b * S_ + seg * SEGL) * D_ + d);
    float* op = out + ((size_t)b * S_ + seg * SEGL) * D_ + d;

    if (pt == 0) {
        float4 acc = carry;
#pragma unroll
        for (int i = 0; i < SEGL; i++) {
            const int j = seg * SEGL + i;
            float4 h4 = h4tof4(__ldg(hp + (size_t)i * (D_ / 4)));
            acc = f4fma(ws[i], h4, acc);
            const float inv = 1.f / (zps[i] * (float)(j + 1));
            st_cs4(op + (size_t)i * D_, f4scale(acc, inv));
        }
    } else if (pt == 1) {
        float4 acc = carry;
#pragma unroll
        for (int i = SEGL - 1; i >= 0; i--) {
            const int j = seg * SEGL + i;
            float4 h4 = h4tof4(__ldg(hp + (size_t)i * (D_ / 4)));
            acc = f4fma(ws[i], h4, acc);
            const float inv = 1.f / (zss[i] * (float)(S_ - j));
            st_cs4(op + (size_t)i * D_, f4scale(acc, inv));
        }
    } else {
        const float ztot = g_zp[b * S_ + (S_ - 1)];
        const float invcnt = 1.f / (float)(S_ - 1);
#pragma unroll
        for (int i = 0; i < SEGL; i++) {
            float4 h4 = h4tof4(__ldg(hp + (size_t)i * (D_ / 4)));
            const float wl = ws[i];
            const float inv = invcnt / (ztot - wl);
            float4 num = f4fma(-wl, h4, carry);
            st_cs4(op + (size_t)i * D_, f4scale(num, inv));
        }
    }
}

// ==============================================================================
extern "C" void kernel_launch(void* const* d_in, const int* in_sizes, int n_in,
                              void* d_out, int out_size)
{
    const float* H   = (const float*)d_in[0];
    const float* W1  = (const float*)d_in[1];
    const float* b1  = (const float*)d_in[2];
    const float* v   = (const float*)d_in[3];
    const int*   pt  = (const int*)  d_in[4];
    float*       out = (float*)d_out;

    cudaFuncSetAttribute(k_scores_hmma, cudaFuncAttributeMaxDynamicSharedMemorySize, SMEM_BYTES);

    k_splitB     <<<512, 256>>>(W1);
    k_scores_hmma<<<(B_ * S_) / 64, 256, SMEM_BYTES>>>(H, b1, v);
    k_prep       <<<B_, S_>>>();
    k_passA      <<<dim3(B_, NSEG), 256>>>();       // launch #4 -> profiled
    k_segscan    <<<dim3(B_, 4), 256>>>();
    k_passB      <<<dim3(B_, NSEG), 256>>>(pt, out);
}

// round 17
// speedup vs baseline: 1.2151x; 1.0180x over previous
#include <cuda_runtime.h>
#include <cuda_fp16.h>
#include <cstdint>

// Problem shape (fixed by dataset): B=16, S=1024, D=1024, A=256
#define B_    16
#define S_    1024
#define D_    1024
#define A_    256
#define NSEG  64
#define SEGL  16      // S_/NSEG

// ---------------- scratch (device globals; no allocation allowed) -------------
__device__ float g_s  [B_ * S_];             // final attention scores
__device__ float g_w  [B_ * S_];             // exp(s - max_b)
__device__ float g_zp [B_ * S_];             // inclusive prefix sum of w
__device__ float g_zs [B_ * S_];             // inclusive suffix sum of w
__device__ float g_ps [B_ * NSEG * D_];      // segment partial sums of w*h
__device__ float g_cp [B_ * NSEG * D_];      // exclusive prefix carries
__device__ float g_cs [B_ * NSEG * D_];      // exclusive suffix carries
__device__ float g_tot[B_ * D_];             // total sum of w*h
__device__ __half g_Hh[(size_t)B_ * S_ * D_]; // fp16 mirror of H (written by GEMM)
// fp16 W1, transposed (n-major), PRE-SWIZZLED: 16 K64-chunks x 32KB.
__device__ uint4 g_Bq[16 * 2048];

// ---------------- small float4 helpers ----------------------------------------
__device__ __forceinline__ float4 f4fma(float s, float4 h, float4 acc) {
    acc.x = fmaf(s, h.x, acc.x); acc.y = fmaf(s, h.y, acc.y);
    acc.z = fmaf(s, h.z, acc.z); acc.w = fmaf(s, h.w, acc.w);
    return acc;
}
__device__ __forceinline__ float4 f4scale(float4 a, float s) {
    return make_float4(a.x * s, a.y * s, a.z * s, a.w * s);
}
// streaming (evict-first) float4 store: written once, never re-read
__device__ __forceinline__ void st_cs4(float* p, float4 v) {
    asm volatile("st.global.cs.v4.f32 [%0], {%1, %2, %3, %4};"
                 :: "l"(p), "f"(v.x), "f"(v.y), "f"(v.z), "f"(v.w) : "memory");
}
// unpack 4 fp16 (as uint2) -> float4
__device__ __forceinline__ float4 h4tof4(uint2 r) {
    const __half2 h01 = *reinterpret_cast<__half2*>(&r.x);
    const __half2 h23 = *reinterpret_cast<__half2*>(&r.y);
    const float2 f01 = __half22float2(h01);
    const float2 f23 = __half22float2(h23);
    return make_float4(f01.x, f01.y, f23.x, f23.y);
}

// ---------------- portable PTX helpers (sm_80-class; no 'a' features) ---------
__device__ __forceinline__ uint32_t smem_u32(const void* p) {
    uint32_t a;
    asm("{ .reg .u64 t; cvta.to.shared.u64 t, %1; cvt.u32.u64 %0, t; }" : "=r"(a) : "l"(p));
    return a;
}
__device__ __forceinline__ void ldsm_x4(uint32_t* r, uint32_t addr) {
    asm volatile("ldmatrix.sync.aligned.m8n8.x4.shared.b16 {%0,%1,%2,%3}, [%4];"
                 : "=r"(r[0]), "=r"(r[1]), "=r"(r[2]), "=r"(r[3]) : "r"(addr));
}
__device__ __forceinline__ void mma_f16(float* c, const uint32_t* a, const uint32_t* b) {
    asm volatile(
        "mma.sync.aligned.m16n8k16.row.col.f32.f16.f16.f32 "
        "{%0,%1,%2,%3}, {%4,%5,%6,%7}, {%8,%9}, {%0,%1,%2,%3};"
        : "+f"(c[0]), "+f"(c[1]), "+f"(c[2]), "+f"(c[3])
        : "r"(a[0]), "r"(a[1]), "r"(a[2]), "r"(a[3]), "r"(b[0]), "r"(b[1]));
}
#define CP_ASYNC16(dst, src) \
    asm volatile("cp.async.cg.shared.global [%0], [%1], 16;" :: "r"(dst), "l"(src))
#define CP_COMMIT() asm volatile("cp.async.commit_group;" ::: "memory")
#define CP_WAIT0()  asm volatile("cp.async.wait_group 0;" ::: "memory")

#define SWZ(x) ((x) ^ (((x) >> 3) & 0x70))

__device__ __forceinline__ float fast_tanh(float z) {
    const float ez = __expf(2.f * z);
    return 1.f - __fdividef(2.f, ez + 1.f);
}
__device__ __forceinline__ uint32_t h2pack(float a, float b) {
    const __half2 h = __floats2half2_rn(a, b);
    return *reinterpret_cast<const uint32_t*>(&h);
}

// ==============================================================================
// k_splitB: W1 [K=1024][N=256] fp32 -> fp16 n-major [n][k], 16 pre-swizzled
// 32KB K64-chunk images (row n = 64 fp16 = 128B).
// ==============================================================================
__global__ __launch_bounds__(256)
void k_splitB(const float* __restrict__ W1)
{
    const int p  = blockIdx.x * 256 + threadIdx.x;   // 0..131071
    const int n  = p & 255;
    const int kp = p >> 8;                           // 0..511
    const int k  = kp * 2;
    const int c  = k >> 6;                           // K64 chunk
    const int kk = k & 63;

    const float x0 = W1[(size_t)k * A_ + n];
    const float x1 = W1[(size_t)(k + 1) * A_ + n];
    char* img = reinterpret_cast<char*>(g_Bq) + (size_t)c * 32768;
    const uint32_t off = SWZ((uint32_t)n * 128 + (uint32_t)kk * 2);
    *reinterpret_cast<uint32_t*>(img + off) = h2pack(x0, x1);
}

// ==============================================================================
// k_scores_hmma: single-product fp16 GEMM via mma.sync.m16n8k16.f16.
// CTA tile 64(M) x 256(N, full), BK=64, 256 threads = 8 warps (2M x 4N),
// warp tile 32x64.  __launch_bounds__(256, 2): 2 CTAs/SM, one wave.
// Converted fp16 A tiles are also persisted to g_Hh (fp16 mirror of H).
// ==============================================================================
#define OFF_V     0
#define OFF_B1    1024
#define OFF_DATA  4096
#define SB_OFF    8192       // B image within stage
#define STAGE_SZ  40960
#define SMEM_BYTES (OFF_DATA + 2 * STAGE_SZ)   // 86016

__global__ __launch_bounds__(256, 2)
void k_scores_hmma(const float* __restrict__ H, const float* __restrict__ b1,
                   const float* __restrict__ v)
{
    extern __shared__ char smem[];
    const uint32_t sb = smem_u32(smem);
    const int tid  = threadIdx.x;
    const int lane = tid & 31;
    const int wid  = tid >> 5;
    const int wm   = (wid & 1) * 32;       // warp M offset (0/32)
    const int wn   = (wid >> 1) * 64;      // warp N offset (0/64/128/192)
    const int m0   = blockIdx.x * 64;

    ((float*)(smem + OFF_V))[tid]  = v[tid];
    ((float*)(smem + OFF_B1))[tid] = b1[tid];

    // ---- A global load mapping: 64 rows x 64 floats, 16 floats per thread ----
    const int arow = tid >> 2;             // 0..63
    const int acol = (tid & 3) * 16;       // 0/16/32/48
    const float4* Ag = reinterpret_cast<const float4*>(H + (size_t)(m0 + arow) * D_ + acol);
    __half* Hh = g_Hh + (size_t)(m0 + arow) * D_ + acol;
    const uint32_t a_sts0 = SWZ((uint32_t)arow * 128 + (uint32_t)acol * 2);
    const uint32_t a_sts1 = SWZ((uint32_t)arow * 128 + (uint32_t)acol * 2 + 16);

    // ---- ldmatrix lane offsets (bytes within tile, pre-swizzle) ----
    uint32_t aoff[2];
#pragma unroll
    for (int mt = 0; mt < 2; mt++)
        aoff[mt] = (uint32_t)(wm + mt * 16 + (lane & 15)) * 128 + (uint32_t)(lane >> 4) * 16;
    const int bn = (lane & 7) + ((lane >> 4) << 3);
    const uint32_t b_kb = (uint32_t)((lane >> 3) & 1) * 16;
    uint32_t boff[4];
#pragma unroll
    for (int np = 0; np < 4; np++)
        boff[np] = (uint32_t)(wn + np * 16 + bn) * 128 + b_kb;

    float acc[2][8][4];
#pragma unroll
    for (int mt = 0; mt < 2; mt++)
#pragma unroll
        for (int nt = 0; nt < 8; nt++)
#pragma unroll
            for (int e = 0; e < 4; e++) acc[mt][nt][e] = 0.f;

    // load this thread's 16 A floats of chunk c, convert, and mirror to g_Hh
    auto loadA = [&](int c, uint4& q0, uint4& q1) {
        float4 x0 = __ldg(Ag + c * 16);
        float4 x1 = __ldg(Ag + c * 16 + 1);
        q0 = make_uint4(h2pack(x0.x, x0.y), h2pack(x0.z, x0.w),
                        h2pack(x1.x, x1.y), h2pack(x1.z, x1.w));
        x0 = __ldg(Ag + c * 16 + 2);
        x1 = __ldg(Ag + c * 16 + 3);
        q1 = make_uint4(h2pack(x0.x, x0.y), h2pack(x0.z, x0.w),
                        h2pack(x1.x, x1.y), h2pack(x1.z, x1.w));
        uint4* dst = reinterpret_cast<uint4*>(Hh + c * 64);
        dst[0] = q0;
        dst[1] = q1;
    };

    // ---- prologue: fill stage 0 ----
    {
        const uint32_t st = sb + OFF_DATA;
#pragma unroll
        for (int u = 0; u < 8; u++)
            CP_ASYNC16(st + SB_OFF + (tid + u * 256) * 16, (const char*)(g_Bq + tid + u * 256));
        CP_COMMIT();
        uint4 q0, q1;
        loadA(0, q0, q1);
        *reinterpret_cast<uint4*>(smem + OFF_DATA + a_sts0) = q0;
        *reinterpret_cast<uint4*>(smem + OFF_DATA + a_sts1) = q1;
        CP_WAIT0();
        __syncthreads();
    }

#pragma unroll 1
    for (int c = 0; c < 16; c++) {
        const uint32_t cur = sb + OFF_DATA + (uint32_t)(c & 1) * STAGE_SZ;
        const uint32_t nxt = sb + OFF_DATA + (uint32_t)((c + 1) & 1) * STAGE_SZ;
        const bool more = (c + 1) < 16;

        uint4 q0, q1;
        if (more) {
#pragma unroll
            for (int u = 0; u < 8; u++)
                CP_ASYNC16(nxt + SB_OFF + (tid + u * 256) * 16,
                           (const char*)(g_Bq + (c + 1) * 2048 + tid + u * 256));
            CP_COMMIT();
            loadA(c + 1, q0, q1);
        }

        // ---- compute: 4 k16 steps per chunk (6 LDSM -> 16 HMMA each) ----
#pragma unroll
        for (int ks = 0; ks < 4; ks++) {
            uint32_t ah[2][4];
#pragma unroll
            for (int mt = 0; mt < 2; mt++)
                ldsm_x4(ah[mt], cur + SWZ(aoff[mt] + ks * 32));
            uint32_t bh[4][4];
#pragma unroll
            for (int np = 0; np < 4; np++)
                ldsm_x4(bh[np], cur + SB_OFF + SWZ(boff[np] + ks * 32));
#pragma unroll
            for (int mt = 0; mt < 2; mt++)
#pragma unroll
                for (int np = 0; np < 4; np++) {
                    mma_f16(acc[mt][np*2],   ah[mt], bh[np]);
                    mma_f16(acc[mt][np*2+1], ah[mt], bh[np] + 2);
                }
        }

        if (more) {
            const uint32_t nxt_off = OFF_DATA + (uint32_t)((c + 1) & 1) * STAGE_SZ;
            *reinterpret_cast<uint4*>(smem + nxt_off + a_sts0) = q0;
            *reinterpret_cast<uint4*>(smem + nxt_off + a_sts1) = q1;
            CP_WAIT0();
            __syncthreads();
        }
    }
    __syncthreads();   // stage area about to be reused as reduction buffer

    // ---- epilogue: s[m] = sum_n v[n] * tanh(acc + b1[n]) ----
    {
        const float* vs  = (const float*)(smem + OFF_V);
        const float* b1s = (const float*)(smem + OFF_B1);
        float* red = (float*)(smem + OFF_DATA);   // [64][4]
        const int nw = wid >> 1;

#pragma unroll
        for (int mt = 0; mt < 2; mt++) {
            float s0 = 0.f, s1 = 0.f;
#pragma unroll
            for (int nt = 0; nt < 8; nt++) {
#pragma unroll
                for (int e = 0; e < 2; e++) {
                    const int col = wn + nt * 8 + (lane & 3) * 2 + e;
                    s0 = fmaf(vs[col], fast_tanh(acc[mt][nt][e]     + b1s[col]), s0);
                    s1 = fmaf(vs[col], fast_tanh(acc[mt][nt][e + 2] + b1s[col]), s1);
                }
            }
            s0 += __shfl_xor_sync(0xffffffffu, s0, 1);
            s0 += __shfl_xor_sync(0xffffffffu, s0, 2);
            s1 += __shfl_xor_sync(0xffffffffu, s1, 1);
            s1 += __shfl_xor_sync(0xffffffffu, s1, 2);
            if ((lane & 3) == 0) {
                const int r0 = wm + mt * 16 + (lane >> 2);
                red[r0 * 4 + nw]       = s0;
                red[(r0 + 8) * 4 + nw] = s1;
            }
        }
        __syncthreads();
        if (tid < 64) {
            const float s = red[tid * 4] + red[tid * 4 + 1] + red[tid * 4 + 2] + red[tid * 4 + 3];
            g_s[m0 + tid] = s;
        }
    }
}

// ==============================================================================
// K2-prep: per batch b — max, w = exp(s - max), inclusive prefix (Zp) and
// inclusive suffix (Zs) scans of w. One block of 1024 threads per batch.
// ==============================================================================
__global__ __launch_bounds__(1024)
void k_prep()
{
    const int b = blockIdx.x;
    const int t = threadIdx.x;
    const int lane = t & 31;
    const int warp = t >> 5;

    __shared__ float sh[S_];
    __shared__ float red[32];
    __shared__ float bmax;

    const int base = b * S_;
    float s = g_s[base + t];

    float m = s;
#pragma unroll
    for (int off = 16; off > 0; off >>= 1)
        m = fmaxf(m, __shfl_xor_sync(0xffffffffu, m, off));
    if (lane == 0) red[warp] = m;
    __syncthreads();
    if (t == 0) {
        float mm = red[0];
        for (int i = 1; i < 32; i++) mm = fmaxf(mm, red[i]);
        bmax = mm;
    }
    __syncthreads();

    const float w = expf(s - bmax);
    g_w[base + t] = w;
    sh[t] = w;
    __syncthreads();

    float ps = w;
#pragma unroll
    for (int off = 1; off < 32; off <<= 1) {
        float n = __shfl_up_sync(0xffffffffu, ps, off);
        if (lane >= off) ps += n;
    }
    if (lane == 31) red[warp] = ps;
    __syncthreads();
    if (warp == 0) {
        float x = red[lane];
#pragma unroll
        for (int off = 1; off < 32; off <<= 1) {
            float n = __shfl_up_sync(0xffffffffu, x, off);
            if (lane >= off) x += n;
        }
        red[lane] = x;
    }
    __syncthreads();
    g_zp[base + t] = ps + (warp ? red[warp - 1] : 0.f);
    __syncthreads();

    float wr = sh[(S_ - 1) - t];
    float pr = wr;
#pragma unroll
    for (int off = 1; off < 32; off <<= 1) {
        float n = __shfl_up_sync(0xffffffffu, pr, off);
        if (lane >= off) pr += n;
    }
    if (lane == 31) red[warp] = pr;
    __syncthreads();
    if (warp == 0) {
        float x = red[lane];
#pragma unroll
        for (int off = 1; off < 32; off <<= 1) {
            float n = __shfl_up_sync(0xffffffffu, x, off);
            if (lane >= off) x += n;
        }
        red[lane] = x;
    }
    __syncthreads();
    g_zs[base + (S_ - 1) - t] = pr + (warp ? red[warp - 1] : 0.f);
}

// ==============================================================================
// K2-passA: segment partial sums  PS[b][seg][d] = sum_{l in seg} w[l]*h[b,l,d]
// Reads the fp16 mirror g_Hh (half the bytes of fp32 H).
// ==============================================================================
__global__ __launch_bounds__(256)
void k_passA()
{
    const int b   = blockIdx.x;
    const int seg = blockIdx.y;
    const int t   = threadIdx.x;
    const int d   = t * 4;

    __shared__ float ws[SEGL];
    if (t < SEGL) ws[t] = g_w[b * S_ + seg * SEGL + t];
    __syncthreads();

    const uint2* hp = reinterpret_cast<const uint2*>(
        g_Hh + ((size_t)b * S_ + seg * SEGL) * D_ + d);
    float4 acc = make_float4(0.f, 0.f, 0.f, 0.f);
#pragma unroll
    for (int l = 0; l < SEGL; l++) {
        float4 h4 = h4tof4(__ldg(hp + (size_t)l * (D_ / 4)));
        acc = f4fma(ws[l], h4, acc);
    }
    *reinterpret_cast<float4*>(&g_ps[((size_t)b * NSEG + seg) * D_ + d]) = acc;
}

// ==============================================================================
// k_segscan: 4-way split scan.  Each (b,d) handled by FOUR threads (16 segs
// each).  Block = 256 threads = 64 d-values x 4 quarters; grid = (B, D/64).
// Quarter totals exchanged via smem; both carry directions written from
// register-cached vals.  4x threads, 4x shorter serial chain vs R16.
// ==============================================================================
__global__ __launch_bounds__(256)
void k_segscan()
{
    const int b    = blockIdx.x;
    const int dloc = threadIdx.x & 63;
    const int q    = threadIdx.x >> 6;        // quarter 0..3
    const int d    = blockIdx.y * 64 + dloc;
    const size_t base = (size_t)b * NSEG * D_ + d;

    __shared__ float tot[4][64];

    float vals[16];
    float sum = 0.f;
#pragma unroll
    for (int i = 0; i < 16; i++) {
        vals[i] = g_ps[base + (size_t)(q * 16 + i) * D_];
        sum += vals[i];
    }
    tot[q][dloc] = sum;
    __syncthreads();

    const float t0 = tot[0][dloc], t1 = tot[1][dloc];
    const float t2 = tot[2][dloc], t3 = tot[3][dloc];

    // exclusive prefix offset for this quarter
    float poff = 0.f;
    if (q >= 1) poff += t0;
    if (q >= 2) poff += t1;
    if (q >= 3) poff += t2;
    // exclusive suffix offset for this quarter
    float soff = 0.f;
    if (q <= 2) soff += t3;
    if (q <= 1) soff += t2;
    if (q <= 0) soff += t1;

    float run = poff;
#pragma unroll
    for (int i = 0; i < 16; i++) {
        g_cp[base + (size_t)(q * 16 + i) * D_] = run;
        run += vals[i];
    }
    run = soff;
#pragma unroll
    for (int i = 15; i >= 0; i--) {
        g_cs[base + (size_t)(q * 16 + i) * D_] = run;
        run += vals[i];
    }
    if (q == 0)
        g_tot[b * D_ + d] = t0 + t1 + t2 + t3;
}

// ==============================================================================
// K2-passB: final pooled output (carries precomputed by k_segscan).
//  pt==0 (prefix):  out[j,d] = P_j[d]            / (Zp_j       * (j+1))
//  pt==1 (postfix): out[j,d] = Sfx_j[d]          / (Zs_j       * (S-j))
//  pt==2 (cloze):   out[j,d] = (T[d]-w_j h[j,d]) / ((Zt - w_j) * (S-1))
// Reads fp16 mirror g_Hh; output via streaming stores.
// ==============================================================================
__global__ __launch_bounds__(256)
void k_passB(const int* __restrict__ pt_ids, float* __restrict__ out)
{
    const int b   = blockIdx.x;
    const int seg = blockIdx.y;
    const int t   = threadIdx.x;
    const int d   = t * 4;
    const int pt  = pt_ids[b];

    __shared__ float ws[SEGL], zps[SEGL], zss[SEGL];
    if (t < SEGL) {
        const int l = seg * SEGL + t;
        ws[t]  = g_w [b * S_ + l];
        zps[t] = g_zp[b * S_ + l];
        zss[t] = g_zs[b * S_ + l];
    }
    __syncthreads();

    const size_t cbase = ((size_t)b * NSEG + seg) * D_ + d;
    float4 carry;
    if (pt == 0)      carry = __ldg(reinterpret_cast<const float4*>(&g_cp[cbase]));
    else if (pt == 1) carry = __ldg(reinterpret_cast<const float4*>(&g_cs[cbase]));
    else              carry = __ldg(reinterpret_cast<const float4*>(&g_tot[b * D_ + d]));

    const uint2* hp = reinterpret_cast<const uint2*>(
        g_Hh + ((size_t)b * S_ + seg * SEGL) * D_ + d);
    float* op = out + ((size_t)b * S_ + seg * SEGL) * D_ + d;

    if (pt == 0) {
        float4 acc = carry;
#pragma unroll
        for (int i = 0; i < SEGL; i++) {
            const int j = seg * SEGL + i;
            float4 h4 = h4tof4(__ldg(hp + (size_t)i * (D_ / 4)));
            acc = f4fma(ws[i], h4, acc);
            const float inv = 1.f / (zps[i] * (float)(j + 1));
            st_cs4(op + (size_t)i * D_, f4scale(acc, inv));
        }
    } else if (pt == 1) {
        float4 acc = carry;
#pragma unroll
        for (int i = SEGL - 1; i >= 0; i--) {
            const int j = seg * SEGL + i;
            float4 h4 = h4tof4(__ldg(hp + (size_t)i * (D_ / 4)));
            acc = f4fma(ws[i], h4, acc);
            const float inv = 1.f / (zss[i] * (float)(S_ - j));
            st_cs4(op + (size_t)i * D_, f4scale(acc, inv));
        }
    } else {
        const float ztot = g_zp[b * S_ + (S_ - 1)];
        const float invcnt = 1.f / (float)(S_ - 1);
#pragma unroll
        for (int i = 0; i < SEGL; i++) {
            float4 h4 = h4tof4(__ldg(hp + (size_t)i * (D_ / 4)));
            const float wl = ws[i];
            const float inv = invcnt / (ztot - wl);
            float4 num = f4fma(-wl, h4, carry);
            st_cs4(op + (size_t)i * D_, f4scale(num, inv));
        }
    }
}

// ==============================================================================
extern "C" void kernel_launch(void* const* d_in, const int* in_sizes, int n_in,
                              void* d_out, int out_size)
{
    const float* H   = (const float*)d_in[0];
    const float* W1  = (const float*)d_in[1];
    const float* b1  = (const float*)d_in[2];
    const float* v   = (const float*)d_in[3];
    const int*   pt  = (const int*)  d_in[4];
    float*       out = (float*)d_out;

    cudaFuncSetAttribute(k_scores_hmma, cudaFuncAttributeMaxDynamicSharedMemorySize, SMEM_BYTES);

    k_splitB     <<<512, 256>>>(W1);
    k_scores_hmma<<<(B_ * S_) / 64, 256, SMEM_BYTES>>>(H, b1, v);
    k_prep       <<<B_, S_>>>();
    k_passA      <<<dim3(B_, NSEG), 256>>>();       // launch #4 -> profiled
    k_segscan    <<<dim3(B_, D_ / 64), 256>>>();
    k_passB      <<<dim3(B_, NSEG), 256>>>(pt, out);
}